// round 1
// baseline (speedup 1.0000x reference)
#include <cuda_runtime.h>
#include <math.h>

#define B 8
#define D 128
#define G 2048
#define L 24
#define GF 1025
#define BD 1024
#define LOG2G 11

// ---------------- scratch (device globals, no allocation) ----------------
__device__ float g_z[B*D*G];          // layernormed x          [b][d][g]
__device__ float g_Xre[GF*BD];        // rfft(z)                [f][b*128+d]
__device__ float g_Xim[GF*BD];
__device__ float g_W[GF*D*D];         // sum_l Phi[l,f]*Theta[l,h,d]  [f][h*128+d]
__device__ float g_Sre[GF*BD];        // spectral GEMM out      [f][b*128+h]
__device__ float g_Sim[GF*BD];
__device__ float g_S[B*D*G];          // irfft result           [b][h][g]
__device__ float g_H[B*2*D*G];        // fc1+gelu               [b][h2][g]

// ---------------- LayerNorm over channel dim D ----------------
__global__ void ln_kernel(const float* __restrict__ x,
                          const float* __restrict__ gamma,
                          const float* __restrict__ beta)
{
    int idx = blockIdx.x * blockDim.x + threadIdx.x;   // over B*G
    int b = idx >> 11;
    int g = idx & (G - 1);
    const float* xp = x + (size_t)b * D * G + g;
    float s = 0.f, s2 = 0.f;
#pragma unroll 8
    for (int d = 0; d < D; d++) { float v = xp[d * G]; s += v; s2 += v * v; }
    float mean = s * (1.f / D);
    float var = s2 * (1.f / D) - mean * mean;
    float inv = rsqrtf(var + 1e-5f);
    float* zp = g_z + (size_t)b * D * G + g;
#pragma unroll 8
    for (int d = 0; d < D; d++) {
        float v = xp[d * G];
        zp[d * G] = (v - mean) * inv * gamma[d] + beta[d];
    }
}

// ---------------- forward FFT (real input, Stockham radix-2, smem) ----------------
__global__ void fft_fwd_kernel()
{
    __shared__ float2 b0[G];
    __shared__ float2 b1[G];
    int bd = blockIdx.x;          // b*128+d
    int t  = threadIdx.x;         // 256
    const float* row = g_z + (size_t)bd * G;
    for (int i = t; i < G; i += 256) b0[i] = make_float2(row[i], 0.f);
    __syncthreads();
    float2* src = b0; float2* dst = b1;
#pragma unroll 1
    for (int s = 0; s < LOG2G; s++) {
        int Ls = 1 << s;
        for (int j = t; j < G / 2; j += 256) {
            int p = j & (Ls - 1);
            int q = j >> s;
            float2 a = src[j];
            float2 c = src[j + G / 2];
            float ang = -3.14159265358979323846f * (float)p / (float)Ls;
            float wi, wr;
            __sincosf(ang, &wi, &wr);
            float2 wb = make_float2(wr * c.x - wi * c.y, wr * c.y + wi * c.x);
            int o = (q << (s + 1)) + p;
            dst[o]      = make_float2(a.x + wb.x, a.y + wb.y);
            dst[o + Ls] = make_float2(a.x - wb.x, a.y - wb.y);
        }
        __syncthreads();
        float2* tmp = src; src = dst; dst = tmp;
    }
    // half-spectrum, transposed layout [f][bd]
    for (int f = t; f < GF; f += 256) {
        g_Xre[(size_t)f * BD + bd] = src[f].x;
        g_Xim[(size_t)f * BD + bd] = src[f].y;
    }
}

// ---------------- W[f,h,d] = sum_l Phi[l,f] * Theta[l,h,d] ----------------
__global__ void wprep_kernel(const float* __restrict__ Phi,
                             const float* __restrict__ Theta)
{
    __shared__ float phis[32][25];
    int f0 = blockIdx.x * 32;
    int i0 = blockIdx.y * 256;
    int t  = threadIdx.x;
    for (int k = t; k < 32 * L; k += 256) {
        int fl = k / L, l = k % L;
        int f = f0 + fl;
        phis[fl][l] = (f < GF) ? Phi[l * GF + f] : 0.f;
    }
    __syncthreads();
    float th[L];
#pragma unroll
    for (int l = 0; l < L; l++) th[l] = Theta[l * (D * D) + i0 + t];
    int fmax = GF - f0; if (fmax > 32) fmax = 32;
    for (int fl = 0; fl < fmax; fl++) {
        float acc = 0.f;
#pragma unroll
        for (int l = 0; l < L; l++) acc += phis[fl][l] * th[l];
        g_W[(size_t)(f0 + fl) * (D * D) + i0 + t] = acc;
    }
}

// ---------------- per-frequency complex GEMM: Sf[f,b,h] = sum_d Xf[f,b,d]*W[f,h,d] ----------------
__global__ void specmm_kernel()
{
    __shared__ float  Wsh[D][65];
    __shared__ float2 xsh[BD];     // (re,im) at [b*128+d]
    int f = blockIdx.x;
    int t = threadIdx.x;           // 256
    const float* Wf = g_W + (size_t)f * (D * D);
    for (int k = t; k < BD; k += 256)
        xsh[k] = make_float2(g_Xre[(size_t)f * BD + k], g_Xim[(size_t)f * BD + k]);
    int h  = t & 127;
    int bh = t >> 7;               // 0/1 -> b in [bh*4, bh*4+4)
    float ar[4] = {0, 0, 0, 0}, ai[4] = {0, 0, 0, 0};
    for (int dc = 0; dc < D; dc += 64) {
        __syncthreads();
        for (int k = t; k < D * 64; k += 256) {
            int hh = k >> 6, dd = k & 63;
            Wsh[hh][dd] = Wf[hh * D + dc + dd];
        }
        __syncthreads();
#pragma unroll 8
        for (int dd = 0; dd < 64; dd++) {
            float w = Wsh[h][dd];
            int dg = dc + dd;
#pragma unroll
            for (int bb = 0; bb < 4; bb++) {
                float2 xv = xsh[(bh * 4 + bb) * D + dg];
                ar[bb] += xv.x * w;
                ai[bb] += xv.y * w;
            }
        }
    }
#pragma unroll
    for (int bb = 0; bb < 4; bb++) {
        size_t o = (size_t)f * BD + (bh * 4 + bb) * D + h;
        g_Sre[o] = ar[bb];
        g_Sim[o] = ai[bb];
    }
}

// ---------------- inverse FFT (Hermitian reconstruct, +twiddle, /G) ----------------
__global__ void fft_inv_kernel()
{
    __shared__ float2 b0[G];
    __shared__ float2 b1[G];
    int bh = blockIdx.x;           // b*128+h
    int t  = threadIdx.x;
    for (int f = t; f < GF; f += 256) {
        float re = g_Sre[(size_t)f * BD + bh];
        float im = g_Sim[(size_t)f * BD + bh];
        b0[f] = make_float2(re, im);
        if (f > 0 && f < G / 2) b0[G - f] = make_float2(re, -im);
    }
    __syncthreads();
    float2* src = b0; float2* dst = b1;
#pragma unroll 1
    for (int s = 0; s < LOG2G; s++) {
        int Ls = 1 << s;
        for (int j = t; j < G / 2; j += 256) {
            int p = j & (Ls - 1);
            int q = j >> s;
            float2 a = src[j];
            float2 c = src[j + G / 2];
            float ang = 3.14159265358979323846f * (float)p / (float)Ls;
            float wi, wr;
            __sincosf(ang, &wi, &wr);
            float2 wb = make_float2(wr * c.x - wi * c.y, wr * c.y + wi * c.x);
            int o = (q << (s + 1)) + p;
            dst[o]      = make_float2(a.x + wb.x, a.y + wb.y);
            dst[o + Ls] = make_float2(a.x - wb.x, a.y - wb.y);
        }
        __syncthreads();
        float2* tmp = src; src = dst; dst = tmp;
    }
    float* out = g_S + (size_t)bh * G;
    for (int g = t; g < G; g += 256) out[g] = src[g].x * (1.0f / G);
}

// ---------------- fc1 + gelu: H[b,h,g] = gelu(w1 @ S + b1) ----------------
__global__ void fc1_kernel(const float* __restrict__ w1, const float* __restrict__ b1)
{
    __shared__ float Ash[32][132];
    __shared__ float Bsh[32][132];
    int b  = blockIdx.z;
    int m0 = blockIdx.y * 128;
    int n0 = blockIdx.x * 128;
    int t  = threadIdx.x;
    int tx = t & 15, ty = t >> 4;
    const float* Sb = g_S + (size_t)b * D * G;
    float acc[8][8] = {};
    for (int kc = 0; kc < D; kc += 32) {
        for (int idx = t; idx < 128 * 32; idx += 256) {
            int m = idx >> 5, k = idx & 31;
            Ash[k][m] = w1[(m0 + m) * D + kc + k];
        }
        for (int idx = t; idx < 32 * 128; idx += 256) {
            int k = idx >> 7, n = idx & 127;
            Bsh[k][n] = Sb[(size_t)(kc + k) * G + n0 + n];
        }
        __syncthreads();
#pragma unroll
        for (int k = 0; k < 32; k++) {
            float4 a0 = *(const float4*)&Ash[k][ty * 8];
            float4 a1 = *(const float4*)&Ash[k][ty * 8 + 4];
            float4 q0 = *(const float4*)&Bsh[k][tx * 8];
            float4 q1 = *(const float4*)&Bsh[k][tx * 8 + 4];
            float av[8] = {a0.x, a0.y, a0.z, a0.w, a1.x, a1.y, a1.z, a1.w};
            float bv[8] = {q0.x, q0.y, q0.z, q0.w, q1.x, q1.y, q1.z, q1.w};
#pragma unroll
            for (int i = 0; i < 8; i++)
#pragma unroll
                for (int j = 0; j < 8; j++) acc[i][j] += av[i] * bv[j];
        }
        __syncthreads();
    }
#pragma unroll
    for (int i = 0; i < 8; i++) {
        int h = m0 + ty * 8 + i;
        float bias = b1[h];
#pragma unroll
        for (int j = 0; j < 8; j++) {
            int g = n0 + tx * 8 + j;
            float v = acc[i][j] + bias;
            g_H[((size_t)b * 256 + h) * G + g] =
                0.5f * v * (1.f + erff(v * 0.7071067811865475f));
        }
    }
}

// ---------------- fc2 + bias + residual: out = x + w2 @ H + b2 ----------------
__global__ void fc2_kernel(const float* __restrict__ w2, const float* __restrict__ b2,
                           const float* __restrict__ x, float* __restrict__ out)
{
    __shared__ float Ash[32][132];
    __shared__ float Bsh[32][132];
    int b  = blockIdx.z;
    int n0 = blockIdx.x * 128;
    int t  = threadIdx.x;
    int tx = t & 15, ty = t >> 4;
    const float* Hb = g_H + (size_t)b * 256 * G;
    float acc[8][8] = {};
    for (int kc = 0; kc < 256; kc += 32) {
        for (int idx = t; idx < 128 * 32; idx += 256) {
            int m = idx >> 5, k = idx & 31;
            Ash[k][m] = w2[m * 256 + kc + k];
        }
        for (int idx = t; idx < 32 * 128; idx += 256) {
            int k = idx >> 7, n = idx & 127;
            Bsh[k][n] = Hb[(size_t)(kc + k) * G + n0 + n];
        }
        __syncthreads();
#pragma unroll
        for (int k = 0; k < 32; k++) {
            float4 a0 = *(const float4*)&Ash[k][ty * 8];
            float4 a1 = *(const float4*)&Ash[k][ty * 8 + 4];
            float4 q0 = *(const float4*)&Bsh[k][tx * 8];
            float4 q1 = *(const float4*)&Bsh[k][tx * 8 + 4];
            float av[8] = {a0.x, a0.y, a0.z, a0.w, a1.x, a1.y, a1.z, a1.w};
            float bv[8] = {q0.x, q0.y, q0.z, q0.w, q1.x, q1.y, q1.z, q1.w};
#pragma unroll
            for (int i = 0; i < 8; i++)
#pragma unroll
                for (int j = 0; j < 8; j++) acc[i][j] += av[i] * bv[j];
        }
        __syncthreads();
    }
#pragma unroll
    for (int i = 0; i < 8; i++) {
        int d = ty * 8 + i;
        float bias = b2[d];
#pragma unroll
        for (int j = 0; j < 8; j++) {
            int g = n0 + tx * 8 + j;
            size_t o = ((size_t)b * D + d) * G + g;
            out[o] = x[o] + acc[i][j] + bias;
        }
    }
}

extern "C" void kernel_launch(void* const* d_in, const int* in_sizes, int n_in,
                              void* d_out, int out_size)
{
    const float* x     = (const float*)d_in[0];
    const float* Phi   = (const float*)d_in[1];
    const float* Theta = (const float*)d_in[2];
    const float* gam   = (const float*)d_in[3];
    const float* bet   = (const float*)d_in[4];
    const float* w1    = (const float*)d_in[5];
    const float* b1    = (const float*)d_in[6];
    const float* w2    = (const float*)d_in[7];
    const float* b2    = (const float*)d_in[8];
    float* out = (float*)d_out;

    ln_kernel<<<128, 128>>>(x, gam, bet);
    fft_fwd_kernel<<<BD, 256>>>();
    wprep_kernel<<<dim3(33, 64), 256>>>(Phi, Theta);
    specmm_kernel<<<GF, 256>>>();
    fft_inv_kernel<<<BD, 256>>>();
    fc1_kernel<<<dim3(16, 2, B), 256>>>(w1, b1);
    fc2_kernel<<<dim3(16, 1, B), 256>>>(w2, b2, x, out);
}

// round 3
// speedup vs baseline: 1.0493x; 1.0493x over previous
#include <cuda_runtime.h>
#include <math.h>

#define B 8
#define D 128
#define G 2048
#define L 24
#define GF 1025
#define BD 1024
#define LOG2G 11

// ---------------- scratch (device globals, no allocation) ----------------
__device__ float  g_z[B*D*G];            // layernormed x          [b][d][g]
__device__ float2 g_Xc[(size_t)GF*BD];   // rfft(z)  (re,im)       [f][b*128+d]
__device__ float  g_W[(size_t)GF*D*D];   // sum_l Phi[l,f]*Theta[l,h,d]  [f][h*128+d]
__device__ float2 g_Sc[(size_t)GF*BD];   // spectral GEMM out      [f][b*128+h]
__device__ float  g_S[B*D*G];            // irfft result           [b][h][g]
__device__ float  g_H[B*2*D*G];          // fc1+gelu               [b][h2][g]

// ---------------- f32x2 helpers ----------------
__device__ __forceinline__ unsigned long long splat2(float v) {
    unsigned long long r; unsigned int u = __float_as_uint(v);
    asm("mov.b64 %0, {%1, %2};" : "=l"(r) : "r"(u), "r"(u));
    return r;
}
__device__ __forceinline__ void fma2(unsigned long long& d, unsigned long long a,
                                     unsigned long long b, unsigned long long c) {
    asm("fma.rn.f32x2 %0, %1, %2, %3;" : "=l"(d) : "l"(a), "l"(b), "l"(c));
}
__device__ __forceinline__ float2 unpack2(unsigned long long v) {
    unsigned int lo, hi;
    asm("mov.b64 {%0, %1}, %2;" : "=r"(lo), "=r"(hi) : "l"(v));
    return make_float2(__uint_as_float(lo), __uint_as_float(hi));
}

// ---------------- LayerNorm over channel dim D ----------------
__global__ void ln_kernel(const float* __restrict__ x,
                          const float* __restrict__ gamma,
                          const float* __restrict__ beta)
{
    int idx = blockIdx.x * blockDim.x + threadIdx.x;   // over B*G
    int b = idx >> 11;
    int g = idx & (G - 1);
    const float* xp = x + (size_t)b * D * G + g;
    float s = 0.f, s2 = 0.f;
#pragma unroll 8
    for (int d = 0; d < D; d++) { float v = xp[d * G]; s += v; s2 += v * v; }
    float mean = s * (1.f / D);
    float var = s2 * (1.f / D) - mean * mean;
    float inv = rsqrtf(var + 1e-5f);
    float* zp = g_z + (size_t)b * D * G + g;
#pragma unroll 8
    for (int d = 0; d < D; d++) {
        float v = xp[d * G];
        zp[d * G] = (v - mean) * inv * gamma[d] + beta[d];
    }
}

// ---------------- forward FFT: two real rows packed into one complex FFT ----------------
// blockIdx.x = b*64 + dp  (dp indexes a pair of channels 2dp, 2dp+1)
__global__ void fft_fwd_kernel()
{
    __shared__ float2 b0[G];
    __shared__ float2 b1[G];
    __shared__ float2 twsh[G / 2];
    int blk = blockIdx.x;
    int b   = blk >> 6;
    int dp  = blk & 63;
    int t   = threadIdx.x;         // 256

    for (int p = t; p < G / 2; p += 256) {
        float s, c;
        __sincosf(-3.14159265358979323846f * (float)p / (float)(G / 2), &s, &c);
        twsh[p] = make_float2(c, s);
    }
    const float* row0 = g_z + ((size_t)b * D + 2 * dp) * G;
    const float* row1 = row0 + G;
    for (int i = t; i < G; i += 256) b0[i] = make_float2(row0[i], row1[i]);
    __syncthreads();

    float2* src = b0; float2* dst = b1;
#pragma unroll 1
    for (int s = 0; s < LOG2G; s++) {
        int Ls = 1 << s;
        for (int j = t; j < G / 2; j += 256) {
            int p = j & (Ls - 1);
            int q = j >> s;
            float2 a = src[j];
            float2 c = src[j + G / 2];
            float2 w = twsh[p << (10 - s)];
            float2 wb = make_float2(w.x * c.x - w.y * c.y, w.x * c.y + w.y * c.x);
            int o = (q << (s + 1)) + p;
            dst[o]      = make_float2(a.x + wb.x, a.y + wb.y);
            dst[o + Ls] = make_float2(a.x - wb.x, a.y - wb.y);
        }
        __syncthreads();
        float2* tmp = src; src = dst; dst = tmp;
    }
    // unpack two real spectra, store transposed [f][bd]
    int col = b * D + 2 * dp;
    for (int f = t; f < GF; f += 256) {
        float2 Yf = src[f];
        float2 Yg = src[(G - f) & (G - 1)];
        float2 Xd  = make_float2(0.5f * (Yf.x + Yg.x), 0.5f * (Yf.y - Yg.y));
        float2 Xd1 = make_float2(0.5f * (Yf.y + Yg.y), 0.5f * (Yg.x - Yf.x));
        g_Xc[(size_t)f * BD + col]     = Xd;
        g_Xc[(size_t)f * BD + col + 1] = Xd1;
    }
}

// ---------------- W[f,h,d] = sum_l Phi[l,f] * Theta[l,h,d] ----------------
__global__ void wprep_kernel(const float* __restrict__ Phi,
                             const float* __restrict__ Theta)
{
    __shared__ float phis[32][25];
    int f0 = blockIdx.x * 32;
    int i0 = blockIdx.y * 256;
    int t  = threadIdx.x;
    for (int k = t; k < 32 * L; k += 256) {
        int fl = k / L, l = k % L;
        int f = f0 + fl;
        phis[fl][l] = (f < GF) ? Phi[l * GF + f] : 0.f;
    }
    __syncthreads();
    float th[L];
#pragma unroll
    for (int l = 0; l < L; l++) th[l] = Theta[l * (D * D) + i0 + t];
    int fmax = GF - f0; if (fmax > 32) fmax = 32;
    for (int fl = 0; fl < fmax; fl++) {
        float acc = 0.f;
#pragma unroll
        for (int l = 0; l < L; l++) acc += phis[fl][l] * th[l];
        g_W[(size_t)(f0 + fl) * (D * D) + i0 + t] = acc;
    }
}

// ---------------- per-frequency complex GEMM with packed f32x2 ----------------
// Sf[f,b,h] = sum_d Xf[f,b,d] * W[f,h,d]   (W real -> re/im share the multiplier)
__global__ void specmm_kernel()
{
    __shared__ __align__(16) float2 xsh[BD];   // 8KB: [b*128+d] (re,im)
    int f = blockIdx.x;
    int t = threadIdx.x;           // 256
    {
        const float4* xg = (const float4*)(g_Xc + (size_t)f * BD);
        float4* xs4 = (float4*)xsh;
        for (int k = t; k < BD / 2; k += 256) xs4[k] = xg[k];
    }
    __syncthreads();
    int h  = t & 127;
    int bh = t >> 7;               // 0/1 -> b in [bh*4, bh*4+4)
    const unsigned long long* xp =
        (const unsigned long long*)(xsh + bh * 4 * D);
    const float4* wrow = (const float4*)(g_W + (size_t)f * D * D + h * D);
    unsigned long long acc[4] = {0ull, 0ull, 0ull, 0ull};
#pragma unroll 4
    for (int i = 0; i < 16; i++) {              // 8 d per iter
        float4 wa = wrow[2 * i];
        float4 wb = wrow[2 * i + 1];
        int d0 = i * 8;
        float wv[8] = {wa.x, wa.y, wa.z, wa.w, wb.x, wb.y, wb.z, wb.w};
#pragma unroll
        for (int j = 0; j < 8; j++) {
            unsigned long long ws = splat2(wv[j]);
#pragma unroll
            for (int bb = 0; bb < 4; bb++) {
                unsigned long long xv = xp[bb * D + d0 + j];  // broadcast LDS.64
                fma2(acc[bb], xv, ws, acc[bb]);
            }
        }
    }
#pragma unroll
    for (int bb = 0; bb < 4; bb++)
        g_Sc[(size_t)f * BD + (bh * 4 + bb) * D + h] = unpack2(acc[bb]);
}

// ---------------- inverse FFT: two Hermitian spectra packed into one complex FFT ----------------
// blockIdx.x = b*64 + hp (pair of output channels 2hp, 2hp+1)
__global__ void fft_inv_kernel()
{
    __shared__ float2 b0[G];
    __shared__ float2 b1[G];
    __shared__ float2 twsh[G / 2];
    int blk = blockIdx.x;
    int b   = blk >> 6;
    int hp  = blk & 63;
    int t   = threadIdx.x;
    for (int p = t; p < G / 2; p += 256) {
        float s, c;
        __sincosf(3.14159265358979323846f * (float)p / (float)(G / 2), &s, &c);
        twsh[p] = make_float2(c, s);
    }
    int col = b * D + 2 * hp;
    for (int f = t; f < GF; f += 256) {
        float2 S0 = g_Sc[(size_t)f * BD + col];
        float2 S1 = g_Sc[(size_t)f * BD + col + 1];
        b0[f] = make_float2(S0.x - S1.y, S0.y + S1.x);
        if (f > 0 && f < G / 2)
            b0[G - f] = make_float2(S0.x + S1.y, S1.x - S0.y);
    }
    __syncthreads();
    float2* src = b0; float2* dst = b1;
#pragma unroll 1
    for (int s = 0; s < LOG2G; s++) {
        int Ls = 1 << s;
        for (int j = t; j < G / 2; j += 256) {
            int p = j & (Ls - 1);
            int q = j >> s;
            float2 a = src[j];
            float2 c = src[j + G / 2];
            float2 w = twsh[p << (10 - s)];
            float2 wb = make_float2(w.x * c.x - w.y * c.y, w.x * c.y + w.y * c.x);
            int o = (q << (s + 1)) + p;
            dst[o]      = make_float2(a.x + wb.x, a.y + wb.y);
            dst[o + Ls] = make_float2(a.x - wb.x, a.y - wb.y);
        }
        __syncthreads();
        float2* tmp = src; src = dst; dst = tmp;
    }
    float* out0 = g_S + (size_t)col * G;
    float* out1 = out0 + G;
    const float sc = 1.0f / G;
    for (int g = t; g < G; g += 256) {
        float2 v = src[g];
        out0[g] = v.x * sc;
        out1[g] = v.y * sc;
    }
}

// ---------------- fc1 + gelu: H[b,h,g] = gelu(w1 @ S + b1), packed f32x2 ----------------
__global__ void fc1_kernel(const float* __restrict__ w1, const float* __restrict__ b1)
{
    __shared__ __align__(16) float Ash[32][132];
    __shared__ __align__(16) float Bsh[32][132];
    int b  = blockIdx.z;
    int m0 = blockIdx.y * 128;
    int n0 = blockIdx.x * 128;
    int t  = threadIdx.x;
    int tx = t & 15, ty = t >> 4;
    const float* Sb = g_S + (size_t)b * D * G;
    unsigned long long acc[8][4] = {};
    for (int kc = 0; kc < D; kc += 32) {
        for (int idx = t; idx < 128 * 32; idx += 256) {
            int m = idx >> 5, k = idx & 31;
            Ash[k][m] = w1[(m0 + m) * D + kc + k];
        }
        for (int idx = t; idx < 32 * 128; idx += 256) {
            int k = idx >> 7, n = idx & 127;
            Bsh[k][n] = Sb[(size_t)(kc + k) * G + n0 + n];
        }
        __syncthreads();
#pragma unroll
        for (int k = 0; k < 32; k++) {
            float4 a0 = *(const float4*)&Ash[k][ty * 8];
            float4 a1 = *(const float4*)&Ash[k][ty * 8 + 4];
            ulonglong2 p0 = *(const ulonglong2*)&Bsh[k][tx * 8];
            ulonglong2 p1 = *(const ulonglong2*)&Bsh[k][tx * 8 + 4];
            unsigned long long bv[4] = {p0.x, p0.y, p1.x, p1.y};
            float av[8] = {a0.x, a0.y, a0.z, a0.w, a1.x, a1.y, a1.z, a1.w};
#pragma unroll
            for (int i = 0; i < 8; i++) {
                unsigned long long ws = splat2(av[i]);
#pragma unroll
                for (int j = 0; j < 4; j++) fma2(acc[i][j], bv[j], ws, acc[i][j]);
            }
        }
        __syncthreads();
    }
#pragma unroll
    for (int i = 0; i < 8; i++) {
        int h = m0 + ty * 8 + i;
        float bias = b1[h];
        float* Hrow = g_H + ((size_t)b * 256 + h) * G + n0 + tx * 8;
#pragma unroll
        for (int j = 0; j < 4; j++) {
            float2 v2 = unpack2(acc[i][j]);
            float v0 = v2.x + bias, v1 = v2.y + bias;
            Hrow[2 * j]     = 0.5f * v0 * (1.f + erff(v0 * 0.7071067811865475f));
            Hrow[2 * j + 1] = 0.5f * v1 * (1.f + erff(v1 * 0.7071067811865475f));
        }
    }
}

// ---------------- fc2 + bias + residual: out = x + w2 @ H + b2, packed f32x2 ----------------
__global__ void fc2_kernel(const float* __restrict__ w2, const float* __restrict__ b2,
                           const float* __restrict__ x, float* __restrict__ out)
{
    __shared__ __align__(16) float Ash[32][132];
    __shared__ __align__(16) float Bsh[32][132];
    int b  = blockIdx.z;
    int n0 = blockIdx.x * 128;
    int t  = threadIdx.x;
    int tx = t & 15, ty = t >> 4;
    const float* Hb = g_H + (size_t)b * 256 * G;
    unsigned long long acc[8][4] = {};
    for (int kc = 0; kc < 256; kc += 32) {
        for (int idx = t; idx < 128 * 32; idx += 256) {
            int m = idx >> 5, k = idx & 31;
            Ash[k][m] = w2[m * 256 + kc + k];
        }
        for (int idx = t; idx < 32 * 128; idx += 256) {
            int k = idx >> 7, n = idx & 127;
            Bsh[k][n] = Hb[(size_t)(kc + k) * G + n0 + n];
        }
        __syncthreads();
#pragma unroll
        for (int k = 0; k < 32; k++) {
            float4 a0 = *(const float4*)&Ash[k][ty * 8];
            float4 a1 = *(const float4*)&Ash[k][ty * 8 + 4];
            ulonglong2 p0 = *(const ulonglong2*)&Bsh[k][tx * 8];
            ulonglong2 p1 = *(const ulonglong2*)&Bsh[k][tx * 8 + 4];
            unsigned long long bv[4] = {p0.x, p0.y, p1.x, p1.y};
            float av[8] = {a0.x, a0.y, a0.z, a0.w, a1.x, a1.y, a1.z, a1.w};
#pragma unroll
            for (int i = 0; i < 8; i++) {
                unsigned long long ws = splat2(av[i]);
#pragma unroll
                for (int j = 0; j < 4; j++) fma2(acc[i][j], bv[j], ws, acc[i][j]);
            }
        }
        __syncthreads();
    }
#pragma unroll
    for (int i = 0; i < 8; i++) {
        int d = ty * 8 + i;
        float bias = b2[d];
        size_t o = ((size_t)b * D + d) * G + n0 + tx * 8;
#pragma unroll
        for (int j = 0; j < 4; j++) {
            float2 v2 = unpack2(acc[i][j]);
            out[o + 2 * j]     = x[o + 2 * j]     + v2.x + bias;
            out[o + 2 * j + 1] = x[o + 2 * j + 1] + v2.y + bias;
        }
    }
}

extern "C" void kernel_launch(void* const* d_in, const int* in_sizes, int n_in,
                              void* d_out, int out_size)
{
    const float* x     = (const float*)d_in[0];
    const float* Phi   = (const float*)d_in[1];
    const float* Theta = (const float*)d_in[2];
    const float* gam   = (const float*)d_in[3];
    const float* bet   = (const float*)d_in[4];
    const float* w1    = (const float*)d_in[5];
    const float* b1    = (const float*)d_in[6];
    const float* w2    = (const float*)d_in[7];
    const float* b2    = (const float*)d_in[8];
    float* out = (float*)d_out;

    ln_kernel<<<128, 128>>>(x, gam, bet);
    fft_fwd_kernel<<<512, 256>>>();
    wprep_kernel<<<dim3(33, 64), 256>>>(Phi, Theta);
    specmm_kernel<<<GF, 256>>>();
    fft_inv_kernel<<<512, 256>>>();
    fc1_kernel<<<dim3(16, 2, B), 256>>>(w1, b1);
    fc2_kernel<<<dim3(16, 1, B), 256>>>(w2, b2, x, out);
}

// round 4
// speedup vs baseline: 1.2181x; 1.1609x over previous
#include <cuda_runtime.h>
#include <math.h>

#define B 8
#define D 128
#define G 2048
#define L 24
#define GF 1025
#define BD 1024
#define LOG2G 11

// ---------------- scratch (device globals, no allocation) ----------------
__device__ float2 g_stat[B*G];           // (mean, rstd) per (b,g)
__device__ float2 g_Xc[(size_t)GF*BD];   // rfft(z)  (re,im)       [f][b*128+d]
__device__ float  g_ThT[L*D*D];          // Theta transposed       [l][d][h]
__device__ float  g_W[(size_t)GF*D*D];   // sum_l Phi*Theta        [f][d][h]  (transposed!)
__device__ float2 g_Sc[(size_t)GF*BD];   // spectral GEMM out      [f][b*128+h]
__device__ float  g_S[B*D*G];            // irfft result           [b][h][g]
__device__ float  g_w1T[D*2*D];          // w1 transposed          [k=128][h=256]
__device__ float  g_w2T[2*D*D];          // w2 transposed          [k=256][d=128]

// ---------------- f32x2 helpers ----------------
__device__ __forceinline__ unsigned long long splat2(float v) {
    unsigned long long r; unsigned int u = __float_as_uint(v);
    asm("mov.b64 %0, {%1, %2};" : "=l"(r) : "r"(u), "r"(u));
    return r;
}
__device__ __forceinline__ void fma2(unsigned long long& d, unsigned long long a,
                                     unsigned long long b, unsigned long long c) {
    asm("fma.rn.f32x2 %0, %1, %2, %3;" : "=l"(d) : "l"(a), "l"(b), "l"(c));
}
__device__ __forceinline__ float2 unpack2(unsigned long long v) {
    unsigned int lo, hi;
    asm("mov.b64 {%0, %1}, %2;" : "=r"(lo), "=r"(hi) : "l"(v));
    return make_float2(__uint_as_float(lo), __uint_as_float(hi));
}

// ---------------- LN stats: mean/rstd over channel dim D per (b,g) ----------------
__global__ void stats_kernel(const float* __restrict__ x)
{
    int idx = blockIdx.x * 256 + threadIdx.x;   // over B*G = 16384
    int b = idx >> 11;
    int g = idx & (G - 1);
    const float* xp = x + (size_t)b * D * G + g;
    float s = 0.f, s2 = 0.f;
#pragma unroll 8
    for (int d = 0; d < D; d++) { float v = xp[d * G]; s += v; s2 += v * v; }
    float mean = s * (1.f / D);
    float var = s2 * (1.f / D) - mean * mean;
    g_stat[idx] = make_float2(mean, rsqrtf(var + 1e-5f));
}

// ---------------- Theta transpose: g_ThT[l][d][h] = Theta[l][h][d] ----------------
__global__ void thetaT_kernel(const float* __restrict__ Theta)
{
    __shared__ float tile[32][33];
    int l  = blockIdx.z;
    int h0 = blockIdx.x * 32, d0 = blockIdx.y * 32;
    int tx = threadIdx.x, ty = threadIdx.y;    // (32,8)
    const float* src = Theta + (size_t)l * D * D;
    for (int i = ty; i < 32; i += 8)
        tile[i][tx] = src[(h0 + i) * D + d0 + tx];
    __syncthreads();
    float* dst = g_ThT + (size_t)l * D * D;
    for (int i = ty; i < 32; i += 8)
        dst[(d0 + i) * D + h0 + tx] = tile[tx][i];
}

// ---------------- weight transposes: w1[256][128]->w1T[128][256], w2[128][256]->w2T[256][128] ----
__global__ void wT_kernel(const float* __restrict__ w1, const float* __restrict__ w2)
{
    __shared__ float tile[32][33];
    int z = blockIdx.z;
    const float* src = z ? w2 : w1;
    float* dst = z ? g_w2T : g_w1T;
    int R = z ? 128 : 256, C = z ? 256 : 128;
    int c0 = blockIdx.x * 32, r0 = blockIdx.y * 32;
    if (c0 >= C || r0 >= R) return;
    int tx = threadIdx.x, ty = threadIdx.y;
    for (int i = ty; i < 32; i += 8) tile[i][tx] = src[(r0 + i) * C + c0 + tx];
    __syncthreads();
    for (int i = ty; i < 32; i += 8) dst[(c0 + i) * R + r0 + tx] = tile[tx][i];
}

// ---------------- forward FFT, LN fused at load; two real rows per complex FFT ----------------
__global__ void fft_fwd_kernel(const float* __restrict__ x,
                               const float* __restrict__ gamma,
                               const float* __restrict__ beta)
{
    __shared__ float2 b0[G];
    __shared__ float2 b1[G];
    __shared__ float2 twsh[G / 2];
    int blk = blockIdx.x;
    int b   = blk >> 6;
    int dp  = blk & 63;
    int t   = threadIdx.x;         // 256
    int d0c = 2 * dp;

    for (int p = t; p < G / 2; p += 256) {
        float s, c;
        __sincosf(-3.14159265358979323846f * (float)p / (float)(G / 2), &s, &c);
        twsh[p] = make_float2(c, s);
    }
    float ga0 = gamma[d0c], ga1 = gamma[d0c + 1];
    float be0 = beta[d0c],  be1 = beta[d0c + 1];
    const float* row0 = x + ((size_t)b * D + d0c) * G;
    const float* row1 = row0 + G;
    const float2* st = g_stat + b * G;
    for (int i = t; i < G; i += 256) {
        float2 s = st[i];
        b0[i] = make_float2((row0[i] - s.x) * s.y * ga0 + be0,
                            (row1[i] - s.x) * s.y * ga1 + be1);
    }
    __syncthreads();

    float2* src = b0; float2* dst = b1;
#pragma unroll 1
    for (int s = 0; s < LOG2G; s++) {
        int Ls = 1 << s;
        for (int j = t; j < G / 2; j += 256) {
            int p = j & (Ls - 1);
            int q = j >> s;
            float2 a = src[j];
            float2 c = src[j + G / 2];
            float2 w = twsh[p << (10 - s)];
            float2 wb = make_float2(w.x * c.x - w.y * c.y, w.x * c.y + w.y * c.x);
            int o = (q << (s + 1)) + p;
            dst[o]      = make_float2(a.x + wb.x, a.y + wb.y);
            dst[o + Ls] = make_float2(a.x - wb.x, a.y - wb.y);
        }
        __syncthreads();
        float2* tmp = src; src = dst; dst = tmp;
    }
    int col = b * D + d0c;
    for (int f = t; f < GF; f += 256) {
        float2 Yf = src[f];
        float2 Yg = src[(G - f) & (G - 1)];
        float2 Xd  = make_float2(0.5f * (Yf.x + Yg.x), 0.5f * (Yf.y - Yg.y));
        float2 Xd1 = make_float2(0.5f * (Yf.y + Yg.y), 0.5f * (Yg.x - Yf.x));
        g_Xc[(size_t)f * BD + col]     = Xd;
        g_Xc[(size_t)f * BD + col + 1] = Xd1;
    }
}

// ---------------- W[f][d][h] = sum_l Phi[l,f] * ThT[l][d][h] ----------------
__global__ void wprep_kernel(const float* __restrict__ Phi)
{
    __shared__ float phis[32][25];
    int f0 = blockIdx.x * 32;
    int i0 = blockIdx.y * 256;
    int t  = threadIdx.x;
    for (int k = t; k < 32 * L; k += 256) {
        int fl = k / L, l = k % L;
        int f = f0 + fl;
        phis[fl][l] = (f < GF) ? Phi[l * GF + f] : 0.f;
    }
    __syncthreads();
    float th[L];
#pragma unroll
    for (int l = 0; l < L; l++) th[l] = g_ThT[l * (D * D) + i0 + t];
    int fmax = GF - f0; if (fmax > 32) fmax = 32;
    for (int fl = 0; fl < fmax; fl++) {
        float acc = 0.f;
#pragma unroll
        for (int l = 0; l < L; l++) acc += phis[fl][l] * th[l];
        g_W[(size_t)(f0 + fl) * (D * D) + i0 + t] = acc;
    }
}

// ---------------- per-frequency complex GEMM: warp-per-f, 8b x 4h register tile ----------------
// Sc[f,b,h] = sum_d Xc[f,b,d] * W[f,d,h]   (W real -> re/im share multiplier via f32x2)
__global__ void __launch_bounds__(256) specmm_kernel()
{
    int warp = threadIdx.x >> 5, lane = threadIdx.x & 31;
    int f = blockIdx.x * 8 + warp;
    if (f >= GF) return;
    const unsigned long long* xp = (const unsigned long long*)(g_Xc + (size_t)f * BD);
    const float4* wp = (const float4*)(g_W + (size_t)f * (D * D));
    unsigned long long acc[8][4];
#pragma unroll
    for (int b = 0; b < 8; b++)
#pragma unroll
        for (int j = 0; j < 4; j++) acc[b][j] = 0ull;

#pragma unroll 2
    for (int d = 0; d < D; d++) {
        float4 w4 = wp[d * 32 + lane];          // W[f][d][lane*4 .. +3], coalesced
        unsigned long long ws0 = splat2(w4.x), ws1 = splat2(w4.y);
        unsigned long long ws2 = splat2(w4.z), ws3 = splat2(w4.w);
#pragma unroll
        for (int b = 0; b < 8; b++) {
            unsigned long long xv = xp[b * 128 + d];   // uniform across warp
            fma2(acc[b][0], xv, ws0, acc[b][0]);
            fma2(acc[b][1], xv, ws1, acc[b][1]);
            fma2(acc[b][2], xv, ws2, acc[b][2]);
            fma2(acc[b][3], xv, ws3, acc[b][3]);
        }
    }
#pragma unroll
    for (int b = 0; b < 8; b++) {
        float2* o = g_Sc + (size_t)f * BD + b * 128 + lane * 4;
        float2 v0 = unpack2(acc[b][0]), v1 = unpack2(acc[b][1]);
        float2 v2 = unpack2(acc[b][2]), v3 = unpack2(acc[b][3]);
        *(float4*)(o)     = make_float4(v0.x, v0.y, v1.x, v1.y);
        *(float4*)(o + 2) = make_float4(v2.x, v2.y, v3.x, v3.y);
    }
}

// ---------------- inverse FFT: two Hermitian spectra packed into one complex FFT ----------------
__global__ void fft_inv_kernel()
{
    __shared__ float2 b0[G];
    __shared__ float2 b1[G];
    __shared__ float2 twsh[G / 2];
    int blk = blockIdx.x;
    int b   = blk >> 6;
    int hp  = blk & 63;
    int t   = threadIdx.x;
    for (int p = t; p < G / 2; p += 256) {
        float s, c;
        __sincosf(3.14159265358979323846f * (float)p / (float)(G / 2), &s, &c);
        twsh[p] = make_float2(c, s);
    }
    int col = b * D + 2 * hp;
    for (int f = t; f < GF; f += 256) {
        float2 S0 = g_Sc[(size_t)f * BD + col];
        float2 S1 = g_Sc[(size_t)f * BD + col + 1];
        b0[f] = make_float2(S0.x - S1.y, S0.y + S1.x);
        if (f > 0 && f < G / 2)
            b0[G - f] = make_float2(S0.x + S1.y, S1.x - S0.y);
    }
    __syncthreads();
    float2* src = b0; float2* dst = b1;
#pragma unroll 1
    for (int s = 0; s < LOG2G; s++) {
        int Ls = 1 << s;
        for (int j = t; j < G / 2; j += 256) {
            int p = j & (Ls - 1);
            int q = j >> s;
            float2 a = src[j];
            float2 c = src[j + G / 2];
            float2 w = twsh[p << (10 - s)];
            float2 wb = make_float2(w.x * c.x - w.y * c.y, w.x * c.y + w.y * c.x);
            int o = (q << (s + 1)) + p;
            dst[o]      = make_float2(a.x + wb.x, a.y + wb.y);
            dst[o + Ls] = make_float2(a.x - wb.x, a.y - wb.y);
        }
        __syncthreads();
        float2* tmp = src; src = dst; dst = tmp;
    }
    float* out0 = g_S + (size_t)col * G;
    float* out1 = out0 + G;
    const float sc = 1.0f / G;
    for (int g = t; g < G; g += 256) {
        float2 v = src[g];
        out0[g] = v.x * sc;
        out1[g] = v.y * sc;
    }
}

// ---------------- fused MLP: out = x + w2 @ gelu(w1 @ S + b1) + b2 ----------------
// grid (G/32, B), block 256. H tile (256x32) lives in smem; no g_H round trip.
__global__ void __launch_bounds__(256) mlp_kernel(const float* __restrict__ b1,
                                                  const float* __restrict__ b2,
                                                  const float* __restrict__ x,
                                                  float* __restrict__ out)
{
    __shared__ float Ssh[128][32];
    __shared__ float Hsh[256][32];
    int b  = blockIdx.y;
    int g0 = blockIdx.x * 32;
    int t  = threadIdx.x;

    // stage S[128 k][32 g]
    const float* Sb = g_S + (size_t)b * D * G + g0;
    for (int idx = t; idx < 128 * 8; idx += 256) {
        int k = idx >> 3, c = idx & 7;
        *(float4*)&Ssh[k][c * 4] = *(const float4*)&Sb[(size_t)k * G + c * 4];
    }
    __syncthreads();

    // phase 1: H[256 h][32 g]; thread = (warp, hy, tx): 8h x 4g tile
    int lane = t & 31, warp = t >> 5;
    int tx = lane & 7;          // g = tx*4 .. +3
    int hy = lane >> 3;         // 0..3
    int h0 = warp * 32 + hy * 8;
    unsigned long long acc[8][2];
#pragma unroll
    for (int i = 0; i < 8; i++) { acc[i][0] = 0ull; acc[i][1] = 0ull; }
#pragma unroll 2
    for (int k = 0; k < 128; k++) {
        float4 wa = *(const float4*)&g_w1T[k * 256 + h0];
        float4 wb = *(const float4*)&g_w1T[k * 256 + h0 + 4];
        unsigned long long s0 = *(const unsigned long long*)&Ssh[k][tx * 4];
        unsigned long long s1 = *(const unsigned long long*)&Ssh[k][tx * 4 + 2];
        float wv[8] = {wa.x, wa.y, wa.z, wa.w, wb.x, wb.y, wb.z, wb.w};
#pragma unroll
        for (int i = 0; i < 8; i++) {
            unsigned long long ws = splat2(wv[i]);
            fma2(acc[i][0], s0, ws, acc[i][0]);
            fma2(acc[i][1], s1, ws, acc[i][1]);
        }
    }
    // gelu + store to Hsh with rotation swizzle: col = (g + ((h>>3)&7)*4) & 31
#pragma unroll
    for (int i = 0; i < 8; i++) {
        int h = h0 + i;
        float bias = b1[h];
        int c0 = (tx * 4 + (((h >> 3) & 7) * 4)) & 31;
        float2 v0 = unpack2(acc[i][0]), v1 = unpack2(acc[i][1]);
        float q0 = v0.x + bias, q1 = v0.y + bias, q2 = v1.x + bias, q3 = v1.y + bias;
        q0 = 0.5f * q0 * (1.f + erff(q0 * 0.7071067811865475f));
        q1 = 0.5f * q1 * (1.f + erff(q1 * 0.7071067811865475f));
        q2 = 0.5f * q2 * (1.f + erff(q2 * 0.7071067811865475f));
        q3 = 0.5f * q3 * (1.f + erff(q3 * 0.7071067811865475f));
        *(float4*)&Hsh[h][c0] = make_float4(q0, q1, q2, q3);
    }
    __syncthreads();

    // phase 2: out[128 d][32 g]; thread = 4d x 4g tile
    int tx2 = t & 7;
    int d0 = (t >> 3) * 4;
    unsigned long long acc2[4][2];
#pragma unroll
    for (int i = 0; i < 4; i++) { acc2[i][0] = 0ull; acc2[i][1] = 0ull; }
#pragma unroll 2
    for (int k = 0; k < 256; k++) {
        float4 wa = *(const float4*)&g_w2T[k * 128 + d0];
        int c0 = (tx2 * 4 + (((k >> 3) & 7) * 4)) & 31;
        unsigned long long h0v = *(const unsigned long long*)&Hsh[k][c0];
        unsigned long long h1v = *(const unsigned long long*)&Hsh[k][c0 + 2];
        float wv[4] = {wa.x, wa.y, wa.z, wa.w};
#pragma unroll
        for (int i = 0; i < 4; i++) {
            unsigned long long ws = splat2(wv[i]);
            fma2(acc2[i][0], h0v, ws, acc2[i][0]);
            fma2(acc2[i][1], h1v, ws, acc2[i][1]);
        }
    }
#pragma unroll
    for (int i = 0; i < 4; i++) {
        int d = d0 + i;
        float bias = b2[d];
        size_t o = ((size_t)b * D + d) * G + g0 + tx2 * 4;
        float2 v0 = unpack2(acc2[i][0]), v1 = unpack2(acc2[i][1]);
        float4 xv = *(const float4*)&x[o];
        *(float4*)&out[o] = make_float4(xv.x + v0.x + bias, xv.y + v0.y + bias,
                                        xv.z + v1.x + bias, xv.w + v1.y + bias);
    }
}

extern "C" void kernel_launch(void* const* d_in, const int* in_sizes, int n_in,
                              void* d_out, int out_size)
{
    const float* x     = (const float*)d_in[0];
    const float* Phi   = (const float*)d_in[1];
    const float* Theta = (const float*)d_in[2];
    const float* gam   = (const float*)d_in[3];
    const float* bet   = (const float*)d_in[4];
    const float* w1    = (const float*)d_in[5];
    const float* b1    = (const float*)d_in[6];
    const float* w2    = (const float*)d_in[7];
    const float* b2    = (const float*)d_in[8];
    float* out = (float*)d_out;

    stats_kernel<<<64, 256>>>(x);
    thetaT_kernel<<<dim3(4, 4, 24), dim3(32, 8)>>>(Theta);
    wT_kernel<<<dim3(8, 8, 2), dim3(32, 8)>>>(w1, w2);
    fft_fwd_kernel<<<512, 256>>>(x, gam, bet);
    wprep_kernel<<<dim3(33, 64), 256>>>(Phi);
    specmm_kernel<<<129, 256>>>();
    fft_inv_kernel<<<512, 256>>>();
    mlp_kernel<<<dim3(64, 8), 256>>>(b1, b2, x, out);
}

// round 5
// speedup vs baseline: 1.3391x; 1.0993x over previous
#include <cuda_runtime.h>
#include <math.h>

#define B 8
#define D 128
#define G 2048
#define L 24
#define GF 1025
#define BD 1024

// ---------------- scratch (device globals, no allocation) ----------------
__device__ float2 g_stat[B*G];           // (mean, rstd) per (b,g)
__device__ float2 g_Xc[(size_t)GF*BD];   // rfft(z)  (re,im)       [f][b*128+d]
__device__ float  g_ThT[L*D*D];          // Theta transposed       [l][d][h]
__device__ float  g_W[(size_t)GF*D*D];   // sum_l Phi*Theta        [f][d][h]
__device__ float2 g_Sc[(size_t)GF*BD];   // spectral GEMM out      [f][b*128+h]
__device__ float2 g_ScT[(size_t)BD*GF];  // transposed             [b*128+h][f]
__device__ float  g_S[B*D*G];            // irfft result           [b][h][g]
__device__ float  g_w1T[D*2*D];          // w1 transposed          [k=128][h=256]
__device__ float  g_w2T[2*D*D];          // w2 transposed          [k=256][d=128]

// ---------------- helpers ----------------
__device__ __forceinline__ unsigned long long splat2(float v) {
    unsigned long long r; unsigned int u = __float_as_uint(v);
    asm("mov.b64 %0, {%1, %2};" : "=l"(r) : "r"(u), "r"(u));
    return r;
}
__device__ __forceinline__ void fma2(unsigned long long& d, unsigned long long a,
                                     unsigned long long b, unsigned long long c) {
    asm("fma.rn.f32x2 %0, %1, %2, %3;" : "=l"(d) : "l"(a), "l"(b), "l"(c));
}
__device__ __forceinline__ float2 unpack2(unsigned long long v) {
    unsigned int lo, hi;
    asm("mov.b64 {%0, %1}, %2;" : "=r"(lo), "=r"(hi) : "l"(v));
    return make_float2(__uint_as_float(lo), __uint_as_float(hi));
}
__device__ __forceinline__ float2 cmul(float2 a, float2 b) {
    return make_float2(a.x * b.x - a.y * b.y, a.x * b.y + a.y * b.x);
}
__device__ __forceinline__ float2 cadd(float2 a, float2 b) { return make_float2(a.x + b.x, a.y + b.y); }
__device__ __forceinline__ float2 csub(float2 a, float2 b) { return make_float2(a.x - b.x, a.y - b.y); }

// ---------------- LN stats ----------------
__global__ void stats_kernel(const float* __restrict__ x)
{
    int idx = blockIdx.x * 256 + threadIdx.x;   // B*G = 16384
    int b = idx >> 11;
    int g = idx & (G - 1);
    const float* xp = x + (size_t)b * D * G + g;
    float s = 0.f, s2 = 0.f;
#pragma unroll 8
    for (int d = 0; d < D; d++) { float v = xp[d * G]; s += v; s2 += v * v; }
    float mean = s * (1.f / D);
    float var = s2 * (1.f / D) - mean * mean;
    g_stat[idx] = make_float2(mean, rsqrtf(var + 1e-5f));
}

// ---------------- Theta transpose: g_ThT[l][d][h] = Theta[l][h][d] ----------------
__global__ void thetaT_kernel(const float* __restrict__ Theta)
{
    __shared__ float tile[32][33];
    int l  = blockIdx.z;
    int h0 = blockIdx.x * 32, d0 = blockIdx.y * 32;
    int tx = threadIdx.x, ty = threadIdx.y;    // (32,8)
    const float* src = Theta + (size_t)l * D * D;
    for (int i = ty; i < 32; i += 8)
        tile[i][tx] = src[(h0 + i) * D + d0 + tx];
    __syncthreads();
    float* dst = g_ThT + (size_t)l * D * D;
    for (int i = ty; i < 32; i += 8)
        dst[(d0 + i) * D + h0 + tx] = tile[tx][i];
}

// ---------------- weight transposes ----------------
__global__ void wT_kernel(const float* __restrict__ w1, const float* __restrict__ w2)
{
    __shared__ float tile[32][33];
    int z = blockIdx.z;
    const float* src = z ? w2 : w1;
    float* dst = z ? g_w2T : g_w1T;
    int R = z ? 128 : 256, C = z ? 256 : 128;
    int c0 = blockIdx.x * 32, r0 = blockIdx.y * 32;
    if (c0 >= C || r0 >= R) return;
    int tx = threadIdx.x, ty = threadIdx.y;
    for (int i = ty; i < 32; i += 8) tile[i][tx] = src[(r0 + i) * C + c0 + tx];
    __syncthreads();
    for (int i = ty; i < 32; i += 8) dst[(c0 + i) * R + r0 + tx] = tile[tx][i];
}

// ---------------- forward FFT: radix-4 Stockham (5x r4 + 1x r2), LN fused, 2 real rows packed ----
__global__ void __launch_bounds__(512) fft_fwd_kernel(const float* __restrict__ x,
                                                      const float* __restrict__ gamma,
                                                      const float* __restrict__ beta)
{
    __shared__ float2 b0[G];
    __shared__ float2 b1[G];
    __shared__ float2 tw[G / 2];
    int blk = blockIdx.x;
    int b   = blk >> 6;
    int dp  = blk & 63;
    int t   = threadIdx.x;         // 512
    int d0c = 2 * dp;

    for (int p = t; p < G / 2; p += 512) {
        float s, c;
        __sincosf(-2.f * 3.14159265358979323846f * (float)p / (float)G, &s, &c);
        tw[p] = make_float2(c, s);
    }
    float ga0 = gamma[d0c], ga1 = gamma[d0c + 1];
    float be0 = beta[d0c],  be1 = beta[d0c + 1];
    const float* row0 = x + ((size_t)b * D + d0c) * G;
    const float* row1 = row0 + G;
    const float2* st = g_stat + b * G;
    for (int i = t; i < G; i += 512) {
        float2 s = st[i];
        b0[i] = make_float2((row0[i] - s.x) * s.y * ga0 + be0,
                            (row1[i] - s.x) * s.y * ga1 + be1);
    }
    __syncthreads();

    float2* src = b0; float2* dst = b1;
#pragma unroll
    for (int s = 0; s < 5; s++) {          // radix-4 stages, Ls = 4^s
        int Ls = 1 << (2 * s);
        int j = t;
        int p = j & (Ls - 1);
        int q = j >> (2 * s);
        float2 t0 = src[j];
        float2 t1 = src[j + 512];
        float2 t2 = src[j + 1024];
        float2 t3 = src[j + 1536];
        float2 w1 = tw[p << (9 - 2 * s)];
        float2 w2 = cmul(w1, w1);
        float2 w3 = cmul(w2, w1);
        t1 = cmul(t1, w1); t2 = cmul(t2, w2); t3 = cmul(t3, w3);
        float2 a02 = cadd(t0, t2), s02 = csub(t0, t2);
        float2 a13 = cadd(t1, t3), s13 = csub(t1, t3);
        int o = (q << (2 * s + 2)) + p;
        dst[o]          = cadd(a02, a13);
        dst[o + Ls]     = make_float2(s02.x + s13.y, s02.y - s13.x);  // s02 - i*s13
        dst[o + 2 * Ls] = csub(a02, a13);
        dst[o + 3 * Ls] = make_float2(s02.x - s13.y, s02.y + s13.x);  // s02 + i*s13
        __syncthreads();
        float2* tmp = src; src = dst; dst = tmp;
    }
    // final radix-2 stage: Ls = 1024
    for (int j = t; j < 1024; j += 512) {
        float2 a = src[j];
        float2 c = src[j + 1024];
        float2 wb = cmul(c, tw[j]);
        dst[j]        = cadd(a, wb);
        dst[j + 1024] = csub(a, wb);
    }
    __syncthreads();
    src = dst;

    int col = b * D + d0c;
    for (int f = t; f < GF; f += 512) {
        float2 Yf = src[f];
        float2 Yg = src[(G - f) & (G - 1)];
        float2 Xd  = make_float2(0.5f * (Yf.x + Yg.x), 0.5f * (Yf.y - Yg.y));
        float2 Xd1 = make_float2(0.5f * (Yf.y + Yg.y), 0.5f * (Yg.x - Yf.x));
        g_Xc[(size_t)f * BD + col]     = Xd;
        g_Xc[(size_t)f * BD + col + 1] = Xd1;
    }
}

// ---------------- W[f][d][h] = sum_l Phi[l,f] * ThT[l][d][h] ----------------
__global__ void wprep_kernel(const float* __restrict__ Phi)
{
    __shared__ float phis[32][25];
    int f0 = blockIdx.x * 32;
    int i0 = blockIdx.y * 256;
    int t  = threadIdx.x;
    for (int k = t; k < 32 * L; k += 256) {
        int fl = k / L, l = k % L;
        int f = f0 + fl;
        phis[fl][l] = (f < GF) ? Phi[l * GF + f] : 0.f;
    }
    __syncthreads();
    float th[L];
#pragma unroll
    for (int l = 0; l < L; l++) th[l] = g_ThT[l * (D * D) + i0 + t];
    int fmax = GF - f0; if (fmax > 32) fmax = 32;
    for (int fl = 0; fl < fmax; fl++) {
        float acc = 0.f;
#pragma unroll
        for (int l = 0; l < L; l++) acc += phis[fl][l] * th[l];
        g_W[(size_t)(f0 + fl) * (D * D) + i0 + t] = acc;
    }
}

// ---------------- per-frequency complex GEMM: warp-per-f, d paired ----------------
__global__ void __launch_bounds__(256) specmm_kernel()
{
    int warp = threadIdx.x >> 5, lane = threadIdx.x & 31;
    int f = blockIdx.x * 8 + warp;
    if (f >= GF) return;
    const ulonglong2* xq = (const ulonglong2*)(g_Xc + (size_t)f * BD);
    const float4* wp = (const float4*)(g_W + (size_t)f * (D * D));
    unsigned long long acc[8][4];
#pragma unroll
    for (int b = 0; b < 8; b++)
#pragma unroll
        for (int j = 0; j < 4; j++) acc[b][j] = 0ull;

#pragma unroll 2
    for (int d = 0; d < D; d += 2) {
        float4 wA = wp[d * 32 + lane];
        float4 wB = wp[(d + 1) * 32 + lane];
        unsigned long long a0 = splat2(wA.x), a1 = splat2(wA.y);
        unsigned long long a2 = splat2(wA.z), a3 = splat2(wA.w);
        unsigned long long c0 = splat2(wB.x), c1 = splat2(wB.y);
        unsigned long long c2 = splat2(wB.z), c3 = splat2(wB.w);
#pragma unroll
        for (int b = 0; b < 8; b++) {
            ulonglong2 xv = xq[b * 64 + (d >> 1)];   // {X_d, X_{d+1}} uniform
            fma2(acc[b][0], xv.x, a0, acc[b][0]);
            fma2(acc[b][1], xv.x, a1, acc[b][1]);
            fma2(acc[b][2], xv.x, a2, acc[b][2]);
            fma2(acc[b][3], xv.x, a3, acc[b][3]);
            fma2(acc[b][0], xv.y, c0, acc[b][0]);
            fma2(acc[b][1], xv.y, c1, acc[b][1]);
            fma2(acc[b][2], xv.y, c2, acc[b][2]);
            fma2(acc[b][3], xv.y, c3, acc[b][3]);
        }
    }
#pragma unroll
    for (int b = 0; b < 8; b++) {
        float2* o = g_Sc + (size_t)f * BD + b * 128 + lane * 4;
        float2 v0 = unpack2(acc[b][0]), v1 = unpack2(acc[b][1]);
        float2 v2 = unpack2(acc[b][2]), v3 = unpack2(acc[b][3]);
        *(float4*)(o)     = make_float4(v0.x, v0.y, v1.x, v1.y);
        *(float4*)(o + 2) = make_float4(v2.x, v2.y, v3.x, v3.y);
    }
}

// ---------------- transpose g_Sc[f][c] -> g_ScT[c][f] ----------------
__global__ void scT_kernel()
{
    __shared__ float2 tile[32][33];
    int f0 = blockIdx.x * 32, c0 = blockIdx.y * 32;
    int tx = threadIdx.x, ty = threadIdx.y;   // (32,8)
    for (int i = ty; i < 32; i += 8) {
        int f = f0 + i;
        if (f < GF) tile[i][tx] = g_Sc[(size_t)f * BD + c0 + tx];
    }
    __syncthreads();
    int f = f0 + tx;
    if (f < GF)
        for (int i = ty; i < 32; i += 8)
            g_ScT[(size_t)(c0 + i) * GF + f] = tile[tx][i];
}

// ---------------- inverse FFT: radix-4 Stockham, 2 Hermitian spectra packed ----------------
__global__ void __launch_bounds__(512) fft_inv_kernel()
{
    __shared__ float2 b0[G];
    __shared__ float2 b1[G];
    __shared__ float2 tw[G / 2];
    int blk = blockIdx.x;
    int b   = blk >> 6;
    int hp  = blk & 63;
    int t   = threadIdx.x;
    for (int p = t; p < G / 2; p += 512) {
        float s, c;
        __sincosf(2.f * 3.14159265358979323846f * (float)p / (float)G, &s, &c);
        tw[p] = make_float2(c, s);
    }
    int col = b * D + 2 * hp;
    const float2* S0p = g_ScT + (size_t)col * GF;
    const float2* S1p = S0p + GF;
    for (int f = t; f < GF; f += 512) {
        float2 S0 = S0p[f];
        float2 S1 = S1p[f];
        b0[f] = make_float2(S0.x - S1.y, S0.y + S1.x);
        if (f > 0 && f < G / 2)
            b0[G - f] = make_float2(S0.x + S1.y, S1.x - S0.y);
    }
    __syncthreads();

    float2* src = b0; float2* dst = b1;
#pragma unroll
    for (int s = 0; s < 5; s++) {
        int Ls = 1 << (2 * s);
        int j = t;
        int p = j & (Ls - 1);
        int q = j >> (2 * s);
        float2 t0 = src[j];
        float2 t1 = src[j + 512];
        float2 t2 = src[j + 1024];
        float2 t3 = src[j + 1536];
        float2 w1 = tw[p << (9 - 2 * s)];
        float2 w2 = cmul(w1, w1);
        float2 w3 = cmul(w2, w1);
        t1 = cmul(t1, w1); t2 = cmul(t2, w2); t3 = cmul(t3, w3);
        float2 a02 = cadd(t0, t2), s02 = csub(t0, t2);
        float2 a13 = cadd(t1, t3), s13 = csub(t1, t3);
        int o = (q << (2 * s + 2)) + p;
        dst[o]          = cadd(a02, a13);
        dst[o + Ls]     = make_float2(s02.x - s13.y, s02.y + s13.x);  // s02 + i*s13
        dst[o + 2 * Ls] = csub(a02, a13);
        dst[o + 3 * Ls] = make_float2(s02.x + s13.y, s02.y - s13.x);  // s02 - i*s13
        __syncthreads();
        float2* tmp = src; src = dst; dst = tmp;
    }
    for (int j = t; j < 1024; j += 512) {
        float2 a = src[j];
        float2 c = src[j + 1024];
        float2 wb = cmul(c, tw[j]);
        dst[j]        = cadd(a, wb);
        dst[j + 1024] = csub(a, wb);
    }
    __syncthreads();
    src = dst;

    float* out0 = g_S + (size_t)col * G;
    float* out1 = out0 + G;
    const float sc = 1.0f / G;
    for (int g = t; g < G; g += 512) {
        float2 v = src[g];
        out0[g] = v.x * sc;
        out1[g] = v.y * sc;
    }
}

// ---------------- fused MLP: out = x + w2 @ gelu(w1 @ S + b1) + b2 ----------------
__global__ void __launch_bounds__(256) mlp_kernel(const float* __restrict__ b1,
                                                  const float* __restrict__ b2,
                                                  const float* __restrict__ x,
                                                  float* __restrict__ out)
{
    __shared__ float Ssh[128][32];
    __shared__ float Hsh[256][32];
    int b  = blockIdx.y;
    int g0 = blockIdx.x * 32;
    int t  = threadIdx.x;

    const float* Sb = g_S + (size_t)b * D * G + g0;
    for (int idx = t; idx < 128 * 8; idx += 256) {
        int k = idx >> 3, c = idx & 7;
        *(float4*)&Ssh[k][c * 4] = *(const float4*)&Sb[(size_t)k * G + c * 4];
    }
    __syncthreads();

    int lane = t & 31, warp = t >> 5;
    int tx = lane & 7;
    int hy = lane >> 3;
    int h0 = warp * 32 + hy * 8;
    unsigned long long acc[8][2];
#pragma unroll
    for (int i = 0; i < 8; i++) { acc[i][0] = 0ull; acc[i][1] = 0ull; }
#pragma unroll 2
    for (int k = 0; k < 128; k++) {
        float4 wa = *(const float4*)&g_w1T[k * 256 + h0];
        float4 wb = *(const float4*)&g_w1T[k * 256 + h0 + 4];
        unsigned long long s0 = *(const unsigned long long*)&Ssh[k][tx * 4];
        unsigned long long s1 = *(const unsigned long long*)&Ssh[k][tx * 4 + 2];
        float wv[8] = {wa.x, wa.y, wa.z, wa.w, wb.x, wb.y, wb.z, wb.w};
#pragma unroll
        for (int i = 0; i < 8; i++) {
            unsigned long long ws = splat2(wv[i]);
            fma2(acc[i][0], s0, ws, acc[i][0]);
            fma2(acc[i][1], s1, ws, acc[i][1]);
        }
    }
#pragma unroll
    for (int i = 0; i < 8; i++) {
        int h = h0 + i;
        float bias = b1[h];
        int c0 = (tx * 4 + (((h >> 3) & 7) * 4)) & 31;
        float2 v0 = unpack2(acc[i][0]), v1 = unpack2(acc[i][1]);
        float q0 = v0.x + bias, q1 = v0.y + bias, q2 = v1.x + bias, q3 = v1.y + bias;
        q0 = 0.5f * q0 * (1.f + erff(q0 * 0.7071067811865475f));
        q1 = 0.5f * q1 * (1.f + erff(q1 * 0.7071067811865475f));
        q2 = 0.5f * q2 * (1.f + erff(q2 * 0.7071067811865475f));
        q3 = 0.5f * q3 * (1.f + erff(q3 * 0.7071067811865475f));
        *(float4*)&Hsh[h][c0] = make_float4(q0, q1, q2, q3);
    }
    __syncthreads();

    int tx2 = t & 7;
    int d0 = (t >> 3) * 4;
    unsigned long long acc2[4][2];
#pragma unroll
    for (int i = 0; i < 4; i++) { acc2[i][0] = 0ull; acc2[i][1] = 0ull; }
#pragma unroll 2
    for (int k = 0; k < 256; k++) {
        float4 wa = *(const float4*)&g_w2T[k * 128 + d0];
        int c0 = (tx2 * 4 + (((k >> 3) & 7) * 4)) & 31;
        unsigned long long h0v = *(const unsigned long long*)&Hsh[k][c0];
        unsigned long long h1v = *(const unsigned long long*)&Hsh[k][c0 + 2];
        float wv[4] = {wa.x, wa.y, wa.z, wa.w};
#pragma unroll
        for (int i = 0; i < 4; i++) {
            unsigned long long ws = splat2(wv[i]);
            fma2(acc2[i][0], h0v, ws, acc2[i][0]);
            fma2(acc2[i][1], h1v, ws, acc2[i][1]);
        }
    }
#pragma unroll
    for (int i = 0; i < 4; i++) {
        int d = d0 + i;
        float bias = b2[d];
        size_t o = ((size_t)b * D + d) * G + g0 + tx2 * 4;
        float2 v0 = unpack2(acc2[i][0]), v1 = unpack2(acc2[i][1]);
        float4 xv = *(const float4*)&x[o];
        *(float4*)&out[o] = make_float4(xv.x + v0.x + bias, xv.y + v0.y + bias,
                                        xv.z + v1.x + bias, xv.w + v1.y + bias);
    }
}

extern "C" void kernel_launch(void* const* d_in, const int* in_sizes, int n_in,
                              void* d_out, int out_size)
{
    const float* x     = (const float*)d_in[0];
    const float* Phi   = (const float*)d_in[1];
    const float* Theta = (const float*)d_in[2];
    const float* gam   = (const float*)d_in[3];
    const float* bet   = (const float*)d_in[4];
    const float* w1    = (const float*)d_in[5];
    const float* b1    = (const float*)d_in[6];
    const float* w2    = (const float*)d_in[7];
    const float* b2    = (const float*)d_in[8];
    float* out = (float*)d_out;

    stats_kernel<<<64, 256>>>(x);
    thetaT_kernel<<<dim3(4, 4, 24), dim3(32, 8)>>>(Theta);
    wT_kernel<<<dim3(8, 8, 2), dim3(32, 8)>>>(w1, w2);
    fft_fwd_kernel<<<512, 512>>>(x, gam, bet);
    wprep_kernel<<<dim3(33, 64), 256>>>(Phi);
    specmm_kernel<<<129, 256>>>();
    scT_kernel<<<dim3(33, 32), dim3(32, 8)>>>();
    fft_inv_kernel<<<512, 512>>>();
    mlp_kernel<<<dim3(64, 8), 256>>>(b1, b2, x, out);
}

// round 6
// speedup vs baseline: 1.3574x; 1.0137x over previous
#include <cuda_runtime.h>
#include <math.h>

#define B 8
#define D 128
#define G 2048
#define L 24
#define GF 1025
#define GFP 1040          // padded ScT row stride (32B-aligned rows)
#define BD 1024

// ---------------- scratch (device globals, no allocation) ----------------
__device__ float2 g_stat[B*G];            // (mean, rstd) per (b,g)
__device__ float2 g_Xc[(size_t)GF*BD];    // rfft(z)                [f][b*128+d]
__device__ float  g_ThT[L*D*D];           // Theta transposed       [l][d][h]
__device__ float  g_W[(size_t)GF*D*D];    // sum_l Phi*Theta        [f][d][h]
__device__ float2 g_Sc[(size_t)GF*BD];    // spectral GEMM out      [f][b*128+h]
__device__ float2 g_ScT[(size_t)BD*GFP];  // transposed             [b*128+h][f]
__device__ float  g_S[B*D*G];             // irfft result           [b][h][g]
__device__ float  g_w1T[D*2*D];           // w1 transposed          [k=128][h=256]
__device__ float  g_w2T[2*D*D];           // w2 transposed          [k=256][d=128]

// ---------------- helpers ----------------
__device__ __forceinline__ unsigned long long splat2(float v) {
    unsigned long long r; unsigned int u = __float_as_uint(v);
    asm("mov.b64 %0, {%1, %2};" : "=l"(r) : "r"(u), "r"(u));
    return r;
}
__device__ __forceinline__ void fma2(unsigned long long& d, unsigned long long a,
                                     unsigned long long b, unsigned long long c) {
    asm("fma.rn.f32x2 %0, %1, %2, %3;" : "=l"(d) : "l"(a), "l"(b), "l"(c));
}
__device__ __forceinline__ float2 unpack2(unsigned long long v) {
    unsigned int lo, hi;
    asm("mov.b64 {%0, %1}, %2;" : "=r"(lo), "=r"(hi) : "l"(v));
    return make_float2(__uint_as_float(lo), __uint_as_float(hi));
}
__device__ __forceinline__ float2 cmul(float2 a, float2 b) {
    return make_float2(a.x * b.x - a.y * b.y, a.x * b.y + a.y * b.x);
}
__device__ __forceinline__ float2 cadd(float2 a, float2 b) { return make_float2(a.x + b.x, a.y + b.y); }
__device__ __forceinline__ float2 csub(float2 a, float2 b) { return make_float2(a.x - b.x, a.y - b.y); }

// ---------------- 2048-pt complex FFT in smem: radix-8 x3 + radix-4 ----------------
// SGN = -1 forward, +1 inverse.  tw[i] = e^{SGN*2*pi*i*i/2048}, i<1024. 256 threads.
template<int SGN>
__device__ __forceinline__ float2* fft2048_body(float2* b0, float2* b1,
                                                const float2* tw, int t)
{
    const float R2 = 0.70710678118654752440f;
    const float2 W1 = make_float2(R2, SGN * R2);
    const float2 W3 = make_float2(-R2, SGN * R2);
    float2* src = b0; float2* dst = b1;
#pragma unroll
    for (int s = 0; s < 3; s++) {
        int Ls = 1 << (3 * s);
        int j = t;
        int p = j & (Ls - 1);
        int q = j >> (3 * s);
        float2 u0 = src[j];
        float2 u1 = src[j + 256],  u2 = src[j + 512],  u3 = src[j + 768];
        float2 u4 = src[j + 1024], u5 = src[j + 1280], u6 = src[j + 1536], u7 = src[j + 1792];
        if (s > 0) {
            float2 w1 = tw[p << (8 - 3 * s)];
            float2 w2 = cmul(w1, w1);
            float2 w3 = cmul(w2, w1);
            float2 w4 = cmul(w2, w2);
            float2 w5 = cmul(w4, w1);
            float2 w6 = cmul(w4, w2);
            float2 w7 = cmul(w4, w3);
            u1 = cmul(u1, w1); u2 = cmul(u2, w2); u3 = cmul(u3, w3);
            u4 = cmul(u4, w4); u5 = cmul(u5, w5); u6 = cmul(u6, w6); u7 = cmul(u7, w7);
        }
        // E = DFT4(u0,u2,u4,u6), O = DFT4(u1,u3,u5,u7)
        float2 es0 = cadd(u0, u4), es1 = csub(u0, u4);
        float2 es2 = cadd(u2, u6), es3 = csub(u2, u6);
        float2 sie = (SGN < 0) ? make_float2(es3.y, -es3.x) : make_float2(-es3.y, es3.x);
        float2 E0 = cadd(es0, es2), E2 = csub(es0, es2);
        float2 E1 = cadd(es1, sie), E3 = csub(es1, sie);
        float2 os0 = cadd(u1, u5), os1 = csub(u1, u5);
        float2 os2 = cadd(u3, u7), os3 = csub(u3, u7);
        float2 sio = (SGN < 0) ? make_float2(os3.y, -os3.x) : make_float2(-os3.y, os3.x);
        float2 O0 = cadd(os0, os2), O2 = csub(os0, os2);
        float2 O1 = cadd(os1, sio), O3 = csub(os1, sio);
        float2 T1 = cmul(W1, O1);
        float2 T2 = (SGN < 0) ? make_float2(O2.y, -O2.x) : make_float2(-O2.y, O2.x);
        float2 T3 = cmul(W3, O3);
        int o = (q << (3 * s + 3)) + p;
        dst[o]          = cadd(E0, O0);
        dst[o + 4 * Ls] = csub(E0, O0);
        dst[o + Ls]     = cadd(E1, T1);
        dst[o + 5 * Ls] = csub(E1, T1);
        dst[o + 2 * Ls] = cadd(E2, T2);
        dst[o + 6 * Ls] = csub(E2, T2);
        dst[o + 3 * Ls] = cadd(E3, T3);
        dst[o + 7 * Ls] = csub(E3, T3);
        __syncthreads();
        float2* tmp = src; src = dst; dst = tmp;
    }
    // final radix-4 stage, Ls = 512
#pragma unroll
    for (int jj = 0; jj < 2; jj++) {
        int j = t + jj * 256;
        float2 t0 = src[j], t1 = src[j + 512], t2 = src[j + 1024], t3 = src[j + 1536];
        float2 w1 = tw[j];
        float2 w2 = tw[2 * j];
        float2 w3 = cmul(w1, w2);
        t1 = cmul(t1, w1); t2 = cmul(t2, w2); t3 = cmul(t3, w3);
        float2 a02 = cadd(t0, t2), s02 = csub(t0, t2);
        float2 a13 = cadd(t1, t3), s13 = csub(t1, t3);
        float2 sis = (SGN < 0) ? make_float2(s13.y, -s13.x) : make_float2(-s13.y, s13.x);
        dst[j]        = cadd(a02, a13);
        dst[j + 512]  = cadd(s02, sis);
        dst[j + 1024] = csub(a02, a13);
        dst[j + 1536] = csub(s02, sis);
    }
    __syncthreads();
    return dst;
}

// ---------------- prep: LN stats + Theta transpose + weight transposes ----------------
__global__ void __launch_bounds__(256) prep_kernel(const float* __restrict__ x,
                                                   const float* __restrict__ Theta,
                                                   const float* __restrict__ w1,
                                                   const float* __restrict__ w2)
{
    __shared__ float tile[32][33];
    int blk = blockIdx.x;
    int t   = threadIdx.x;
    if (blk < 64) {
        // LN stats over channel dim
        int idx = blk * 256 + t;
        int b = idx >> 11;
        int g = idx & (G - 1);
        const float* xp = x + (size_t)b * D * G + g;
        float s = 0.f, s2 = 0.f;
#pragma unroll 8
        for (int d = 0; d < D; d++) { float v = xp[d * G]; s += v; s2 += v * v; }
        float mean = s * (1.f / D);
        float var = s2 * (1.f / D) - mean * mean;
        g_stat[idx] = make_float2(mean, rsqrtf(var + 1e-5f));
    } else if (blk < 448) {
        // Theta transpose: g_ThT[l][d][h] = Theta[l][h][d]
        int blk2 = blk - 64;
        int l = blk2 >> 4;
        int rem = blk2 & 15;
        int h0 = (rem & 3) * 32, d0 = (rem >> 2) * 32;
        int tx = t & 31, ty = t >> 5;
        const float* src = Theta + (size_t)l * D * D;
        for (int i = ty; i < 32; i += 8)
            tile[i][tx] = src[(h0 + i) * D + d0 + tx];
        __syncthreads();
        float* dst = g_ThT + (size_t)l * D * D;
        for (int i = ty; i < 32; i += 8)
            dst[(d0 + i) * D + h0 + tx] = tile[tx][i];
    } else {
        // weight transposes
        int blk3 = blk - 448;
        int z = blk3 >> 6;
        int rem = blk3 & 63;
        const float* src = z ? w2 : w1;
        float* dst = z ? g_w2T : g_w1T;
        int R = z ? 128 : 256, C = z ? 256 : 128;
        int c0 = (rem & 7) * 32, r0 = (rem >> 3) * 32;
        if (c0 >= C || r0 >= R) return;
        int tx = t & 31, ty = t >> 5;
        for (int i = ty; i < 32; i += 8) tile[i][tx] = src[(r0 + i) * C + c0 + tx];
        __syncthreads();
        for (int i = ty; i < 32; i += 8) dst[(c0 + i) * R + r0 + tx] = tile[tx][i];
    }
}

// ---------------- forward FFT (LN fused) + wprep, merged launch ----------------
__global__ void __launch_bounds__(256) fwd_wprep_kernel(const float* __restrict__ x,
                                                        const float* __restrict__ gamma,
                                                        const float* __restrict__ beta,
                                                        const float* __restrict__ Phi)
{
    __shared__ float2 b0[G];
    __shared__ float2 b1[G];
    __shared__ float2 tw[G / 2];
    __shared__ float phis[32][25];
    int blk = blockIdx.x;
    int t   = threadIdx.x;      // 256

    if (blk < 512) {
        // ---- forward FFT: 2 real rows packed, LN fused at load ----
        int b  = blk >> 6;
        int dp = blk & 63;
        int d0c = 2 * dp;
        for (int p = t; p < G / 2; p += 256) {
            float s, c;
            __sincosf(-3.14159265358979323846f * (float)p / 1024.f, &s, &c);
            tw[p] = make_float2(c, s);
        }
        float ga0 = gamma[d0c], ga1 = gamma[d0c + 1];
        float be0 = beta[d0c],  be1 = beta[d0c + 1];
        const float* row0 = x + ((size_t)b * D + d0c) * G;
        const float* row1 = row0 + G;
        const float2* st = g_stat + b * G;
        for (int i = t; i < G; i += 256) {
            float2 s = st[i];
            b0[i] = make_float2((row0[i] - s.x) * s.y * ga0 + be0,
                                (row1[i] - s.x) * s.y * ga1 + be1);
        }
        __syncthreads();
        float2* res = fft2048_body<-1>(b0, b1, tw, t);
        int col = b * D + d0c;
        for (int f = t; f < GF; f += 256) {
            float2 Yf = res[f];
            float2 Yg = res[(G - f) & (G - 1)];
            float2 Xd  = make_float2(0.5f * (Yf.x + Yg.x), 0.5f * (Yf.y - Yg.y));
            float2 Xd1 = make_float2(0.5f * (Yf.y + Yg.y), 0.5f * (Yg.x - Yf.x));
            g_Xc[(size_t)f * BD + col]     = Xd;
            g_Xc[(size_t)f * BD + col + 1] = Xd1;
        }
    } else {
        // ---- wprep: W[f][d][h] = sum_l Phi[l,f] * ThT[l][d][h] ----
        int fid = blk - 512;             // [0, 33*64)
        int f0 = (fid >> 6) * 32;
        int i0 = (fid & 63) * 256;
        for (int k = t; k < 32 * L; k += 256) {
            int fl = k / L, l = k % L;
            int f = f0 + fl;
            phis[fl][l] = (f < GF) ? Phi[l * GF + f] : 0.f;
        }
        __syncthreads();
        float th[L];
#pragma unroll
        for (int l = 0; l < L; l++) th[l] = g_ThT[l * (D * D) + i0 + t];
        int fmax = GF - f0; if (fmax > 32) fmax = 32;
        for (int fl = 0; fl < fmax; fl++) {
            float acc = 0.f;
#pragma unroll
            for (int l = 0; l < L; l++) acc += phis[fl][l] * th[l];
            g_W[(size_t)(f0 + fl) * (D * D) + i0 + t] = acc;
        }
    }
}

// ---------------- per-frequency complex GEMM: warp-per-f, d paired ----------------
__global__ void __launch_bounds__(256) specmm_kernel()
{
    int warp = threadIdx.x >> 5, lane = threadIdx.x & 31;
    int f = blockIdx.x * 8 + warp;
    if (f >= GF) return;
    const ulonglong2* xq = (const ulonglong2*)(g_Xc + (size_t)f * BD);
    const float4* wp = (const float4*)(g_W + (size_t)f * (D * D));
    unsigned long long acc[8][4];
#pragma unroll
    for (int b = 0; b < 8; b++)
#pragma unroll
        for (int j = 0; j < 4; j++) acc[b][j] = 0ull;

#pragma unroll 2
    for (int d = 0; d < D; d += 2) {
        float4 wA = wp[d * 32 + lane];
        float4 wB = wp[(d + 1) * 32 + lane];
        unsigned long long a0 = splat2(wA.x), a1 = splat2(wA.y);
        unsigned long long a2 = splat2(wA.z), a3 = splat2(wA.w);
        unsigned long long c0 = splat2(wB.x), c1 = splat2(wB.y);
        unsigned long long c2 = splat2(wB.z), c3 = splat2(wB.w);
#pragma unroll
        for (int b = 0; b < 8; b++) {
            ulonglong2 xv = xq[b * 64 + (d >> 1)];
            fma2(acc[b][0], xv.x, a0, acc[b][0]);
            fma2(acc[b][1], xv.x, a1, acc[b][1]);
            fma2(acc[b][2], xv.x, a2, acc[b][2]);
            fma2(acc[b][3], xv.x, a3, acc[b][3]);
            fma2(acc[b][0], xv.y, c0, acc[b][0]);
            fma2(acc[b][1], xv.y, c1, acc[b][1]);
            fma2(acc[b][2], xv.y, c2, acc[b][2]);
            fma2(acc[b][3], xv.y, c3, acc[b][3]);
        }
    }
#pragma unroll
    for (int b = 0; b < 8; b++) {
        float2* o = g_Sc + (size_t)f * BD + b * 128 + lane * 4;
        float2 v0 = unpack2(acc[b][0]), v1 = unpack2(acc[b][1]);
        float2 v2 = unpack2(acc[b][2]), v3 = unpack2(acc[b][3]);
        *(float4*)(o)     = make_float4(v0.x, v0.y, v1.x, v1.y);
        *(float4*)(o + 2) = make_float4(v2.x, v2.y, v3.x, v3.y);
    }
}

// ---------------- transpose g_Sc[f][c] -> g_ScT[c][f] (padded stride) ----------------
__global__ void scT_kernel()
{
    __shared__ float2 tile[32][33];
    int f0 = blockIdx.x * 32, c0 = blockIdx.y * 32;
    int t = threadIdx.x;
    int tx = t & 31, ty = t >> 5;   // (32,8)
    for (int i = ty; i < 32; i += 8) {
        int f = f0 + i;
        if (f < GF) tile[i][tx] = g_Sc[(size_t)f * BD + c0 + tx];
    }
    __syncthreads();
    int f = f0 + tx;
    if (f < GF)
        for (int i = ty; i < 32; i += 8)
            g_ScT[(size_t)(c0 + i) * GFP + f] = tile[tx][i];
}

// ---------------- inverse FFT: 2 Hermitian spectra packed ----------------
__global__ void __launch_bounds__(256) fft_inv_kernel()
{
    __shared__ float2 b0[G];
    __shared__ float2 b1[G];
    __shared__ float2 tw[G / 2];
    int blk = blockIdx.x;
    int b   = blk >> 6;
    int hp  = blk & 63;
    int t   = threadIdx.x;
    for (int p = t; p < G / 2; p += 256) {
        float s, c;
        __sincosf(3.14159265358979323846f * (float)p / 1024.f, &s, &c);
        tw[p] = make_float2(c, s);
    }
    int col = b * D + 2 * hp;
    const float2* S0p = g_ScT + (size_t)col * GFP;
    const float2* S1p = S0p + GFP;
    for (int f = t; f < GF; f += 256) {
        float2 S0 = S0p[f];
        float2 S1 = S1p[f];
        b0[f] = make_float2(S0.x - S1.y, S0.y + S1.x);
        if (f > 0 && f < G / 2)
            b0[G - f] = make_float2(S0.x + S1.y, S1.x - S0.y);
    }
    __syncthreads();
    float2* res = fft2048_body<1>(b0, b1, tw, t);
    float* out0 = g_S + (size_t)col * G;
    float* out1 = out0 + G;
    const float sc = 1.0f / G;
    for (int g = t; g < G; g += 256) {
        float2 v = res[g];
        out0[g] = v.x * sc;
        out1[g] = v.y * sc;
    }
}

// ---------------- fused MLP: out = x + w2 @ gelu(w1 @ S + b1) + b2 ----------------
__global__ void __launch_bounds__(256) mlp_kernel(const float* __restrict__ b1,
                                                  const float* __restrict__ b2,
                                                  const float* __restrict__ x,
                                                  float* __restrict__ out)
{
    __shared__ float Ssh[128][32];
    __shared__ float Hsh[256][32];
    int b  = blockIdx.y;
    int g0 = blockIdx.x * 32;
    int t  = threadIdx.x;

    const float* Sb = g_S + (size_t)b * D * G + g0;
    for (int idx = t; idx < 128 * 8; idx += 256) {
        int k = idx >> 3, c = idx & 7;
        *(float4*)&Ssh[k][c * 4] = *(const float4*)&Sb[(size_t)k * G + c * 4];
    }
    __syncthreads();

    int lane = t & 31, warp = t >> 5;
    int tx = lane & 7;
    int hy = lane >> 3;
    int h0 = warp * 32 + hy * 8;
    unsigned long long acc[8][2];
#pragma unroll
    for (int i = 0; i < 8; i++) { acc[i][0] = 0ull; acc[i][1] = 0ull; }
#pragma unroll 2
    for (int k = 0; k < 128; k++) {
        float4 wa = *(const float4*)&g_w1T[k * 256 + h0];
        float4 wb = *(const float4*)&g_w1T[k * 256 + h0 + 4];
        unsigned long long s0 = *(const unsigned long long*)&Ssh[k][tx * 4];
        unsigned long long s1 = *(const unsigned long long*)&Ssh[k][tx * 4 + 2];
        float wv[8] = {wa.x, wa.y, wa.z, wa.w, wb.x, wb.y, wb.z, wb.w};
#pragma unroll
        for (int i = 0; i < 8; i++) {
            unsigned long long ws = splat2(wv[i]);
            fma2(acc[i][0], s0, ws, acc[i][0]);
            fma2(acc[i][1], s1, ws, acc[i][1]);
        }
    }
#pragma unroll
    for (int i = 0; i < 8; i++) {
        int h = h0 + i;
        float bias = b1[h];
        int c0 = (tx * 4 + (((h >> 3) & 7) * 4)) & 31;
        float2 v0 = unpack2(acc[i][0]), v1 = unpack2(acc[i][1]);
        float q0 = v0.x + bias, q1 = v0.y + bias, q2 = v1.x + bias, q3 = v1.y + bias;
        q0 = 0.5f * q0 * (1.f + erff(q0 * 0.7071067811865475f));
        q1 = 0.5f * q1 * (1.f + erff(q1 * 0.7071067811865475f));
        q2 = 0.5f * q2 * (1.f + erff(q2 * 0.7071067811865475f));
        q3 = 0.5f * q3 * (1.f + erff(q3 * 0.7071067811865475f));
        *(float4*)&Hsh[h][c0] = make_float4(q0, q1, q2, q3);
    }
    __syncthreads();

    int tx2 = t & 7;
    int d0 = (t >> 3) * 4;
    unsigned long long acc2[4][2];
#pragma unroll
    for (int i = 0; i < 4; i++) { acc2[i][0] = 0ull; acc2[i][1] = 0ull; }
#pragma unroll 2
    for (int k = 0; k < 256; k++) {
        float4 wa = *(const float4*)&g_w2T[k * 128 + d0];
        int c0 = (tx2 * 4 + (((k >> 3) & 7) * 4)) & 31;
        unsigned long long h0v = *(const unsigned long long*)&Hsh[k][c0];
        unsigned long long h1v = *(const unsigned long long*)&Hsh[k][c0 + 2];
        float wv[4] = {wa.x, wa.y, wa.z, wa.w};
#pragma unroll
        for (int i = 0; i < 4; i++) {
            unsigned long long ws = splat2(wv[i]);
            fma2(acc2[i][0], h0v, ws, acc2[i][0]);
            fma2(acc2[i][1], h1v, ws, acc2[i][1]);
        }
    }
#pragma unroll
    for (int i = 0; i < 4; i++) {
        int d = d0 + i;
        float bias = b2[d];
        size_t o = ((size_t)b * D + d) * G + g0 + tx2 * 4;
        float2 v0 = unpack2(acc2[i][0]), v1 = unpack2(acc2[i][1]);
        float4 xv = *(const float4*)&x[o];
        *(float4*)&out[o] = make_float4(xv.x + v0.x + bias, xv.y + v0.y + bias,
                                        xv.z + v1.x + bias, xv.w + v1.y + bias);
    }
}

extern "C" void kernel_launch(void* const* d_in, const int* in_sizes, int n_in,
                              void* d_out, int out_size)
{
    const float* x     = (const float*)d_in[0];
    const float* Phi   = (const float*)d_in[1];
    const float* Theta = (const float*)d_in[2];
    const float* gam   = (const float*)d_in[3];
    const float* bet   = (const float*)d_in[4];
    const float* w1    = (const float*)d_in[5];
    const float* b1    = (const float*)d_in[6];
    const float* w2    = (const float*)d_in[7];
    const float* b2    = (const float*)d_in[8];
    float* out = (float*)d_out;

    prep_kernel<<<576, 256>>>(x, Theta, w1, w2);
    fwd_wprep_kernel<<<512 + 33 * 64, 256>>>(x, gam, bet, Phi);
    specmm_kernel<<<129, 256>>>();
    scT_kernel<<<dim3(33, 32), 256>>>();
    fft_inv_kernel<<<512, 256>>>();
    mlp_kernel<<<dim3(64, 8), 256>>>(b1, b2, x, out);
}

// round 7
// speedup vs baseline: 1.4810x; 1.0911x over previous
#include <cuda_runtime.h>
#include <cuda_fp16.h>
#include <math.h>

#define B 8
#define D 128
#define G 2048
#define L 24
#define GF 1025
#define GFP 1040          // padded ScT row stride
#define BD 1024

// ---------------- scratch (device globals, no allocation) ----------------
__device__ float2  g_stat[B*G];            // (mean, rstd) per (b,g)
__device__ float2  g_Xc[(size_t)GF*BD];    // rfft(z)                [f][b*128+d]
__device__ float2  g_ThT2[L*64*D];         // Theta d-paired         [l][d2][h] = {Th[2d2][h],Th[2d2+1][h]}
__device__ __half2 g_Wh[(size_t)GF*64*D];  // fp16 W d-paired        [f][d2][h]
__device__ float2  g_ScT[(size_t)BD*GFP];  // spectral out transposed [b*128+h][f]
__device__ float   g_S[B*D*G];             // irfft result           [b][h][g]
__device__ float   g_w1T[D*2*D];           // w1 transposed          [k=128][h=256]
__device__ float   g_w2T[2*D*D];           // w2 transposed          [k=256][d=128]

// ---------------- helpers ----------------
__device__ __forceinline__ unsigned long long splat2(float v) {
    unsigned long long r; unsigned int u = __float_as_uint(v);
    asm("mov.b64 %0, {%1, %2};" : "=l"(r) : "r"(u), "r"(u));
    return r;
}
__device__ __forceinline__ void fma2(unsigned long long& d, unsigned long long a,
                                     unsigned long long b, unsigned long long c) {
    asm("fma.rn.f32x2 %0, %1, %2, %3;" : "=l"(d) : "l"(a), "l"(b), "l"(c));
}
__device__ __forceinline__ float2 unpack2(unsigned long long v) {
    unsigned int lo, hi;
    asm("mov.b64 {%0, %1}, %2;" : "=r"(lo), "=r"(hi) : "l"(v));
    return make_float2(__uint_as_float(lo), __uint_as_float(hi));
}
__device__ __forceinline__ float2 cmul(float2 a, float2 b) {
    return make_float2(a.x * b.x - a.y * b.y, a.x * b.y + a.y * b.x);
}
__device__ __forceinline__ float2 cadd(float2 a, float2 b) { return make_float2(a.x + b.x, a.y + b.y); }
__device__ __forceinline__ float2 csub(float2 a, float2 b) { return make_float2(a.x - b.x, a.y - b.y); }

// ---------------- 2048-pt complex FFT in smem: radix-8 x3 + radix-4, 256 threads ----------------
template<int SGN>
__device__ __forceinline__ float2* fft2048_body(float2* b0, float2* b1,
                                                const float2* tw, int t)
{
    const float R2 = 0.70710678118654752440f;
    const float2 W1 = make_float2(R2, SGN * R2);
    const float2 W3 = make_float2(-R2, SGN * R2);
    float2* src = b0; float2* dst = b1;
#pragma unroll
    for (int s = 0; s < 3; s++) {
        int Ls = 1 << (3 * s);
        int j = t;
        int p = j & (Ls - 1);
        int q = j >> (3 * s);
        float2 u0 = src[j];
        float2 u1 = src[j + 256],  u2 = src[j + 512],  u3 = src[j + 768];
        float2 u4 = src[j + 1024], u5 = src[j + 1280], u6 = src[j + 1536], u7 = src[j + 1792];
        if (s > 0) {
            float2 w1 = tw[p << (8 - 3 * s)];
            float2 w2 = cmul(w1, w1);
            float2 w3 = cmul(w2, w1);
            float2 w4 = cmul(w2, w2);
            float2 w5 = cmul(w4, w1);
            float2 w6 = cmul(w4, w2);
            float2 w7 = cmul(w4, w3);
            u1 = cmul(u1, w1); u2 = cmul(u2, w2); u3 = cmul(u3, w3);
            u4 = cmul(u4, w4); u5 = cmul(u5, w5); u6 = cmul(u6, w6); u7 = cmul(u7, w7);
        }
        float2 es0 = cadd(u0, u4), es1 = csub(u0, u4);
        float2 es2 = cadd(u2, u6), es3 = csub(u2, u6);
        float2 sie = (SGN < 0) ? make_float2(es3.y, -es3.x) : make_float2(-es3.y, es3.x);
        float2 E0 = cadd(es0, es2), E2 = csub(es0, es2);
        float2 E1 = cadd(es1, sie), E3 = csub(es1, sie);
        float2 os0 = cadd(u1, u5), os1 = csub(u1, u5);
        float2 os2 = cadd(u3, u7), os3 = csub(u3, u7);
        float2 sio = (SGN < 0) ? make_float2(os3.y, -os3.x) : make_float2(-os3.y, os3.x);
        float2 O0 = cadd(os0, os2), O2 = csub(os0, os2);
        float2 O1 = cadd(os1, sio), O3 = csub(os1, sio);
        float2 T1 = cmul(W1, O1);
        float2 T2 = (SGN < 0) ? make_float2(O2.y, -O2.x) : make_float2(-O2.y, O2.x);
        float2 T3 = cmul(W3, O3);
        int o = (q << (3 * s + 3)) + p;
        dst[o]          = cadd(E0, O0);
        dst[o + 4 * Ls] = csub(E0, O0);
        dst[o + Ls]     = cadd(E1, T1);
        dst[o + 5 * Ls] = csub(E1, T1);
        dst[o + 2 * Ls] = cadd(E2, T2);
        dst[o + 6 * Ls] = csub(E2, T2);
        dst[o + 3 * Ls] = cadd(E3, T3);
        dst[o + 7 * Ls] = csub(E3, T3);
        __syncthreads();
        float2* tmp = src; src = dst; dst = tmp;
    }
#pragma unroll
    for (int jj = 0; jj < 2; jj++) {
        int j = t + jj * 256;
        float2 t0 = src[j], t1 = src[j + 512], t2 = src[j + 1024], t3 = src[j + 1536];
        float2 w1 = tw[j];
        float2 w2 = tw[2 * j];
        float2 w3 = cmul(w1, w2);
        t1 = cmul(t1, w1); t2 = cmul(t2, w2); t3 = cmul(t3, w3);
        float2 a02 = cadd(t0, t2), s02 = csub(t0, t2);
        float2 a13 = cadd(t1, t3), s13 = csub(t1, t3);
        float2 sis = (SGN < 0) ? make_float2(s13.y, -s13.x) : make_float2(-s13.y, s13.x);
        dst[j]        = cadd(a02, a13);
        dst[j + 512]  = cadd(s02, sis);
        dst[j + 1024] = csub(a02, a13);
        dst[j + 1536] = csub(s02, sis);
    }
    __syncthreads();
    return dst;
}

// ---------------- prep: LN stats + Theta d-paired transpose + weight transposes ----------------
__global__ void __launch_bounds__(256) prep_kernel(const float* __restrict__ x,
                                                   const float* __restrict__ Theta,
                                                   const float* __restrict__ w1,
                                                   const float* __restrict__ w2)
{
    __shared__ float tile[32][33];
    int blk = blockIdx.x;
    int t   = threadIdx.x;
    if (blk < 64) {
        int idx = blk * 256 + t;
        int b = idx >> 11;
        int g = idx & (G - 1);
        const float* xp = x + (size_t)b * D * G + g;
        float s = 0.f, s2 = 0.f;
#pragma unroll 8
        for (int d = 0; d < D; d++) { float v = xp[d * G]; s += v; s2 += v * v; }
        float mean = s * (1.f / D);
        float var = s2 * (1.f / D) - mean * mean;
        g_stat[idx] = make_float2(mean, rsqrtf(var + 1e-5f));
    } else if (blk < 448) {
        // Theta transpose into d-paired float2: g_ThT2[l][d2][h] = {Th[l,h,2d2], Th[l,h,2d2+1]}
        int blk2 = blk - 64;
        int l = blk2 >> 4;
        int rem = blk2 & 15;
        int h0 = (rem & 3) * 32, d0 = (rem >> 2) * 32;
        int tx = t & 31, ty = t >> 5;
        const float* src = Theta + (size_t)l * D * D;
        for (int i = ty; i < 32; i += 8)
            tile[i][tx] = src[(h0 + i) * D + d0 + tx];   // tile[h_loc][d_loc]
        __syncthreads();
        float2* dst = g_ThT2 + (size_t)l * 64 * D;
        for (int i2 = ty; i2 < 16; i2 += 8) {
            int d2 = (d0 >> 1) + i2;
            dst[d2 * D + h0 + tx] = make_float2(tile[tx][2 * i2], tile[tx][2 * i2 + 1]);
        }
    } else {
        int blk3 = blk - 448;
        int z = blk3 >> 6;
        int rem = blk3 & 63;
        const float* src = z ? w2 : w1;
        float* dst = z ? g_w2T : g_w1T;
        int R = z ? 128 : 256, C = z ? 256 : 128;
        int c0 = (rem & 7) * 32, r0 = (rem >> 3) * 32;
        if (c0 >= C || r0 >= R) return;
        int tx = t & 31, ty = t >> 5;
        for (int i = ty; i < 32; i += 8) tile[i][tx] = src[(r0 + i) * C + c0 + tx];
        __syncthreads();
        for (int i = ty; i < 32; i += 8) dst[(c0 + i) * R + r0 + tx] = tile[tx][i];
    }
}

// ---------------- forward FFT (LN fused) + wprep (fp16 W), merged launch ----------------
__global__ void __launch_bounds__(256) fwd_wprep_kernel(const float* __restrict__ x,
                                                        const float* __restrict__ gamma,
                                                        const float* __restrict__ beta,
                                                        const float* __restrict__ Phi)
{
    __shared__ float2 b0[G];
    __shared__ float2 b1[G];
    __shared__ float2 tw[G / 2];
    __shared__ float phis[32][25];
    int blk = blockIdx.x;
    int t   = threadIdx.x;      // 256

    if (blk < 512) {
        int b  = blk >> 6;
        int dp = blk & 63;
        int d0c = 2 * dp;
        for (int p = t; p < G / 2; p += 256) {
            float s, c;
            __sincosf(-3.14159265358979323846f * (float)p / 1024.f, &s, &c);
            tw[p] = make_float2(c, s);
        }
        float ga0 = gamma[d0c], ga1 = gamma[d0c + 1];
        float be0 = beta[d0c],  be1 = beta[d0c + 1];
        const float* row0 = x + ((size_t)b * D + d0c) * G;
        const float* row1 = row0 + G;
        const float2* st = g_stat + b * G;
        for (int i = t; i < G; i += 256) {
            float2 s = st[i];
            b0[i] = make_float2((row0[i] - s.x) * s.y * ga0 + be0,
                                (row1[i] - s.x) * s.y * ga1 + be1);
        }
        __syncthreads();
        float2* res = fft2048_body<-1>(b0, b1, tw, t);
        int col = b * D + d0c;
        for (int f = t; f < GF; f += 256) {
            float2 Yf = res[f];
            float2 Yg = res[(G - f) & (G - 1)];
            float2 Xd  = make_float2(0.5f * (Yf.x + Yg.x), 0.5f * (Yf.y - Yg.y));
            float2 Xd1 = make_float2(0.5f * (Yf.y + Yg.y), 0.5f * (Yg.x - Yf.x));
            g_Xc[(size_t)f * BD + col]     = Xd;
            g_Xc[(size_t)f * BD + col + 1] = Xd1;
        }
    } else {
        // wprep: Wh[f][d2][h] = half2{ sum_l Phi[l,f]*ThT2[l][d2][h].x , ... .y }
        int fid = blk - 512;             // [0, 33*32)
        int f0 = (fid >> 5) * 32;
        int i0 = (fid & 31) * 256;       // over 64*128 = 8192 half2 elems
        for (int k = t; k < 32 * L; k += 256) {
            int fl = k / L, l = k % L;
            int f = f0 + fl;
            phis[fl][l] = (f < GF) ? Phi[l * GF + f] : 0.f;
        }
        __syncthreads();
        float2 th[L];
#pragma unroll
        for (int l = 0; l < L; l++) th[l] = g_ThT2[l * (64 * D) + i0 + t];
        int fmax = GF - f0; if (fmax > 32) fmax = 32;
        for (int fl = 0; fl < fmax; fl++) {
            float2 acc = make_float2(0.f, 0.f);
#pragma unroll
            for (int l = 0; l < L; l++) {
                float p = phis[fl][l];
                acc.x += p * th[l].x;
                acc.y += p * th[l].y;
            }
            g_Wh[(size_t)(f0 + fl) * (64 * D) + i0 + t] = __float22half2_rn(acc);
        }
    }
}

// ---------------- per-frequency complex GEMM: warp-per-f, fp16 W, transposed epilogue ----------------
__global__ void __launch_bounds__(256) specmm_kernel()
{
    __shared__ float2 sm[128][9];
    int warp = threadIdx.x >> 5, lane = threadIdx.x & 31;
    int f0 = blockIdx.x * 8;
    int f = f0 + warp;
    int fc = (f < GF) ? f : (GF - 1);       // clamp; invalid warps do harmless work
    const ulonglong2* xq = (const ulonglong2*)(g_Xc + (size_t)fc * BD);
    const uint4* wp = (const uint4*)(g_Wh + (size_t)fc * (64 * D));
    unsigned long long acc[8][4];
#pragma unroll
    for (int b = 0; b < 8; b++)
#pragma unroll
        for (int j = 0; j < 4; j++) acc[b][j] = 0ull;

#pragma unroll 2
    for (int i = 0; i < 64; i++) {          // d2 = i, covers d = 2i, 2i+1
        uint4 w = wp[i * 32 + lane];        // 4x half2 {W[2i][h], W[2i+1][h]}, h=lane*4..+3
        const __half2* hh = (const __half2*)&w;
        float2 w0 = __half22float2(hh[0]);
        float2 w1 = __half22float2(hh[1]);
        float2 w2 = __half22float2(hh[2]);
        float2 w3 = __half22float2(hh[3]);
        unsigned long long a0 = splat2(w0.x), c0 = splat2(w0.y);
        unsigned long long a1 = splat2(w1.x), c1 = splat2(w1.y);
        unsigned long long a2 = splat2(w2.x), c2 = splat2(w2.y);
        unsigned long long a3 = splat2(w3.x), c3 = splat2(w3.y);
#pragma unroll
        for (int b = 0; b < 8; b++) {
            ulonglong2 xv = xq[b * 64 + i];  // {X_2i, X_2i+1} uniform across warp
            fma2(acc[b][0], xv.x, a0, acc[b][0]);
            fma2(acc[b][1], xv.x, a1, acc[b][1]);
            fma2(acc[b][2], xv.x, a2, acc[b][2]);
            fma2(acc[b][3], xv.x, a3, acc[b][3]);
            fma2(acc[b][0], xv.y, c0, acc[b][0]);
            fma2(acc[b][1], xv.y, c1, acc[b][1]);
            fma2(acc[b][2], xv.y, c2, acc[b][2]);
            fma2(acc[b][3], xv.y, c3, acc[b][3]);
        }
    }

    // transposed epilogue: ScT[c][f], c = b*128 + h. 64B-contiguous stores over f.
    int nf = GF - f0; if (nf > 8) nf = 8;
    int t = threadIdx.x;
#pragma unroll 1
    for (int b = 0; b < 8; b++) {
        __syncthreads();
#pragma unroll
        for (int j = 0; j < 4; j++)
            sm[lane * 4 + j][warp] = unpack2(acc[b][j]);
        __syncthreads();
        if (t < 128) {
            float2* dst = g_ScT + (size_t)(b * 128 + t) * GFP + f0;
            if (nf == 8) {
                float4* d4 = (float4*)dst;
                const float2* s = sm[t];
                d4[0] = make_float4(s[0].x, s[0].y, s[1].x, s[1].y);
                d4[1] = make_float4(s[2].x, s[2].y, s[3].x, s[3].y);
                d4[2] = make_float4(s[4].x, s[4].y, s[5].x, s[5].y);
                d4[3] = make_float4(s[6].x, s[6].y, s[7].x, s[7].y);
            } else {
                for (int k = 0; k < nf; k++) dst[k] = sm[t][k];
            }
        }
    }
}

// ---------------- inverse FFT: 2 Hermitian spectra packed ----------------
__global__ void __launch_bounds__(256) fft_inv_kernel()
{
    __shared__ float2 b0[G];
    __shared__ float2 b1[G];
    __shared__ float2 tw[G / 2];
    int blk = blockIdx.x;
    int b   = blk >> 6;
    int hp  = blk & 63;
    int t   = threadIdx.x;
    for (int p = t; p < G / 2; p += 256) {
        float s, c;
        __sincosf(3.14159265358979323846f * (float)p / 1024.f, &s, &c);
        tw[p] = make_float2(c, s);
    }
    int col = b * D + 2 * hp;
    const float2* S0p = g_ScT + (size_t)col * GFP;
    const float2* S1p = S0p + GFP;
    for (int f = t; f < GF; f += 256) {
        float2 S0 = S0p[f];
        float2 S1 = S1p[f];
        b0[f] = make_float2(S0.x - S1.y, S0.y + S1.x);
        if (f > 0 && f < G / 2)
            b0[G - f] = make_float2(S0.x + S1.y, S1.x - S0.y);
    }
    __syncthreads();
    float2* res = fft2048_body<1>(b0, b1, tw, t);
    float* out0 = g_S + (size_t)col * G;
    float* out1 = out0 + G;
    const float sc = 1.0f / G;
    for (int g = t; g < G; g += 256) {
        float2 v = res[g];
        out0[g] = v.x * sc;
        out1[g] = v.y * sc;
    }
}

// ---------------- fused MLP: out = x + w2 @ gelu(w1 @ S + b1) + b2 ----------------
__global__ void __launch_bounds__(256) mlp_kernel(const float* __restrict__ b1,
                                                  const float* __restrict__ b2,
                                                  const float* __restrict__ x,
                                                  float* __restrict__ out)
{
    __shared__ float Ssh[128][32];
    __shared__ float Hsh[256][32];
    int b  = blockIdx.y;
    int g0 = blockIdx.x * 32;
    int t  = threadIdx.x;

    const float* Sb = g_S + (size_t)b * D * G + g0;
    for (int idx = t; idx < 128 * 8; idx += 256) {
        int k = idx >> 3, c = idx & 7;
        *(float4*)&Ssh[k][c * 4] = *(const float4*)&Sb[(size_t)k * G + c * 4];
    }
    __syncthreads();

    int lane = t & 31, warp = t >> 5;
    int tx = lane & 7;
    int hy = lane >> 3;
    int h0 = warp * 32 + hy * 8;
    unsigned long long acc[8][2];
#pragma unroll
    for (int i = 0; i < 8; i++) { acc[i][0] = 0ull; acc[i][1] = 0ull; }
#pragma unroll 2
    for (int k = 0; k < 128; k++) {
        float4 wa = *(const float4*)&g_w1T[k * 256 + h0];
        float4 wb = *(const float4*)&g_w1T[k * 256 + h0 + 4];
        unsigned long long s0 = *(const unsigned long long*)&Ssh[k][tx * 4];
        unsigned long long s1 = *(const unsigned long long*)&Ssh[k][tx * 4 + 2];
        float wv[8] = {wa.x, wa.y, wa.z, wa.w, wb.x, wb.y, wb.z, wb.w};
#pragma unroll
        for (int i = 0; i < 8; i++) {
            unsigned long long ws = splat2(wv[i]);
            fma2(acc[i][0], s0, ws, acc[i][0]);
            fma2(acc[i][1], s1, ws, acc[i][1]);
        }
    }
#pragma unroll
    for (int i = 0; i < 8; i++) {
        int h = h0 + i;
        float bias = b1[h];
        int c0 = (tx * 4 + (((h >> 3) & 7) * 4)) & 31;
        float2 v0 = unpack2(acc[i][0]), v1 = unpack2(acc[i][1]);
        float q0 = v0.x + bias, q1 = v0.y + bias, q2 = v1.x + bias, q3 = v1.y + bias;
        q0 = 0.5f * q0 * (1.f + erff(q0 * 0.7071067811865475f));
        q1 = 0.5f * q1 * (1.f + erff(q1 * 0.7071067811865475f));
        q2 = 0.5f * q2 * (1.f + erff(q2 * 0.7071067811865475f));
        q3 = 0.5f * q3 * (1.f + erff(q3 * 0.7071067811865475f));
        *(float4*)&Hsh[h][c0] = make_float4(q0, q1, q2, q3);
    }
    __syncthreads();

    int tx2 = t & 7;
    int d0 = (t >> 3) * 4;
    unsigned long long acc2[4][2];
#pragma unroll
    for (int i = 0; i < 4; i++) { acc2[i][0] = 0ull; acc2[i][1] = 0ull; }
#pragma unroll 2
    for (int k = 0; k < 256; k++) {
        float4 wa = *(const float4*)&g_w2T[k * 128 + d0];
        int c0 = (tx2 * 4 + (((k >> 3) & 7) * 4)) & 31;
        unsigned long long h0v = *(const unsigned long long*)&Hsh[k][c0];
        unsigned long long h1v = *(const unsigned long long*)&Hsh[k][c0 + 2];
        float wv[4] = {wa.x, wa.y, wa.z, wa.w};
#pragma unroll
        for (int i = 0; i < 4; i++) {
            unsigned long long ws = splat2(wv[i]);
            fma2(acc2[i][0], h0v, ws, acc2[i][0]);
            fma2(acc2[i][1], h1v, ws, acc2[i][1]);
        }
    }
#pragma unroll
    for (int i = 0; i < 4; i++) {
        int d = d0 + i;
        float bias = b2[d];
        size_t o = ((size_t)b * D + d) * G + g0 + tx2 * 4;
        float2 v0 = unpack2(acc2[i][0]), v1 = unpack2(acc2[i][1]);
        float4 xv = *(const float4*)&x[o];
        *(float4*)&out[o] = make_float4(xv.x + v0.x + bias, xv.y + v0.y + bias,
                                        xv.z + v1.x + bias, xv.w + v1.y + bias);
    }
}

extern "C" void kernel_launch(void* const* d_in, const int* in_sizes, int n_in,
                              void* d_out, int out_size)
{
    const float* x     = (const float*)d_in[0];
    const float* Phi   = (const float*)d_in[1];
    const float* Theta = (const float*)d_in[2];
    const float* gam   = (const float*)d_in[3];
    const float* bet   = (const float*)d_in[4];
    const float* w1    = (const float*)d_in[5];
    const float* b1    = (const float*)d_in[6];
    const float* w2    = (const float*)d_in[7];
    const float* b2    = (const float*)d_in[8];
    float* out = (float*)d_out;

    prep_kernel<<<576, 256>>>(x, Theta, w1, w2);
    fwd_wprep_kernel<<<512 + 33 * 32, 256>>>(x, gam, bet, Phi);
    specmm_kernel<<<129, 256>>>();
    fft_inv_kernel<<<512, 256>>>();
    mlp_kernel<<<dim3(64, 8), 256>>>(b1, b2, x, out);
}